// round 1
// baseline (speedup 1.0000x reference)
#include <cuda_runtime.h>
#include <cstdint>

// ProductVectorQuantizer: inputs [256,512,64] f32, embedding [1024,64] f32.
// Outputs (concatenated float32 in d_out):
//   [0 .. N*D)        quantized_sg  (N = 131072, D = 64)
//   [N*D .. N*D+N)    encoding_indices (as float)
//   [N*D+N .. +2N)    quantization_loss = 1.25 * sum((q-x)^2)
//
// Strategy: per-thread row; codes staged through smem in 128-code tiles;
// distance scores via packed fma.rn.f32x2 (2x fp32 FFMA throughput on sm_103a);
// score = ||e||^2 - 2 x.e (row-constant ||x||^2 dropped for argmin).

#define DIM 64
#define KCODES 1024
#define NROWS (256*512)
#define THREADS 128
#define TILE_K 128
#define NTILES (KCODES / TILE_K)

__device__ __forceinline__ void fma2(unsigned long long& d,
                                     unsigned long long a,
                                     unsigned long long b) {
    asm("fma.rn.f32x2 %0, %1, %2, %0;" : "+l"(d) : "l"(a), "l"(b));
}
__device__ __forceinline__ void add2(unsigned long long& d, unsigned long long a) {
    asm("add.rn.f32x2 %0, %0, %1;" : "+l"(d) : "l"(a));
}

__global__ __launch_bounds__(THREADS)
void vq_kernel(const float* __restrict__ inputs,
               const float* __restrict__ emb,
               float* __restrict__ out_q,
               float* __restrict__ out_idx,
               float* __restrict__ out_loss) {
    __shared__ float s_tile[TILE_K * DIM];   // 32 KB code tile
    __shared__ float s_c[KCODES];            // 4 KB  ||e_k||^2

    const int tid = threadIdx.x;
    const int row = blockIdx.x * THREADS + tid;

    // --- precompute ||e_k||^2 (8 codes per thread, L2-hot) ---
    for (int k = tid; k < KCODES; k += THREADS) {
        const float4* e4 = (const float4*)(emb + (size_t)k * DIM);
        float s = 0.f;
#pragma unroll
        for (int j = 0; j < 16; j++) {
            float4 v = e4[j];
            s += v.x * v.x + v.y * v.y + v.z * v.z + v.w * v.w;
        }
        s_c[k] = s;
    }

    // --- load this thread's row into registers as 32 packed f32x2 ---
    unsigned long long xr[32];
    {
        const ulonglong2* xp = (const ulonglong2*)(inputs + (size_t)row * DIM);
#pragma unroll
        for (int j = 0; j < 16; j++) {
            ulonglong2 v = xp[j];
            xr[2 * j + 0] = v.x;
            xr[2 * j + 1] = v.y;
        }
    }

    float best = 3.4e38f;
    int bidx = 0;

    for (int t = 0; t < NTILES; t++) {
        __syncthreads();
        // stage 128 codes (32 KB) into smem: 2048 float4, 16 per thread
        {
            const float4* g4 = (const float4*)(emb + (size_t)t * TILE_K * DIM);
            float4* s4 = (float4*)s_tile;
#pragma unroll
            for (int j = 0; j < (TILE_K * DIM / 4) / THREADS; j++)
                s4[j * THREADS + tid] = g4[j * THREADS + tid];
        }
        __syncthreads();

#pragma unroll 2
        for (int k = 0; k < TILE_K; k++) {
            const ulonglong2* e2 = (const ulonglong2*)(s_tile + k * DIM);
            unsigned long long a0 = 0ull, a1 = 0ull, a2 = 0ull, a3 = 0ull;
#pragma unroll
            for (int j = 0; j < 16; j += 2) {
                ulonglong2 v0 = e2[j];
                ulonglong2 v1 = e2[j + 1];
                fma2(a0, xr[2 * j + 0], v0.x);
                fma2(a1, xr[2 * j + 1], v0.y);
                fma2(a2, xr[2 * j + 2], v1.x);
                fma2(a3, xr[2 * j + 3], v1.y);
            }
            add2(a0, a1);
            add2(a2, a3);
            add2(a0, a2);
            float lo = __uint_as_float((unsigned)(a0 & 0xFFFFFFFFull));
            float hi = __uint_as_float((unsigned)(a0 >> 32));
            float dot = lo + hi;
            int kk = t * TILE_K + k;
            float score = s_c[kk] - 2.0f * dot;
            if (score < best) { best = score; bidx = kk; }
        }
    }

    // --- exact epilogue: gather winner, loss, straight-through output ---
    {
        const float4* e4 = (const float4*)(emb + (size_t)bidx * DIM);
        const float4* x4 = (const float4*)(inputs + (size_t)row * DIM);
        float4* o4 = (float4*)(out_q + (size_t)row * DIM);
        float loss = 0.f;
#pragma unroll
        for (int j = 0; j < 16; j++) {
            float4 xv = x4[j];
            float4 ev = e4[j];
            float dx = ev.x - xv.x;
            float dy = ev.y - xv.y;
            float dz = ev.z - xv.z;
            float dw = ev.w - xv.w;
            loss += dx * dx + dy * dy + dz * dz + dw * dw;
            o4[j] = make_float4(xv.x + dx, xv.y + dy, xv.z + dz, xv.w + dw);
        }
        out_idx[row] = (float)bidx;
        out_loss[row] = 1.25f * loss;
    }
}

extern "C" void kernel_launch(void* const* d_in, const int* in_sizes, int n_in,
                              void* d_out, int out_size) {
    const float* inputs = (const float*)d_in[0];
    const float* emb = (const float*)d_in[1];
    float* out = (float*)d_out;

    float* out_q = out;                           // N*D
    float* out_idx = out + (size_t)NROWS * DIM;   // N
    float* out_loss = out_idx + NROWS;            // N

    vq_kernel<<<NROWS / THREADS, THREADS>>>(inputs, emb, out_q, out_idx, out_loss);
}

// round 3
// speedup vs baseline: 2.5699x; 2.5699x over previous
#include <cuda_runtime.h>
#include <cuda_fp16.h>
#include <cstdint>

// VQ argmin via HMMA (mma.sync m16n8k16 f16->f32) with exact 2-way fp16 split.
// score(row,k) = ||e_k||^2 + dot(x_row, -2*e_k); x and -2e each split as h + l
// (fp16); all 4 products (hh,lh,hl,ll) accumulated in fp32 => fp32-class error.

#define DIM 64
#define KCODES 1024
#define NROWS (256*512)
#define ROWS_PER_CTA 256
#define THREADS 256
#define NWARP 8
#define CHUNK 128
#define NCHUNK (KCODES / CHUNK)

// B smem rows padded to 72 halves (144 B) -> conflict-free ldmatrix
#define BSTRIDE 144
#define BUF_SPLIT (CHUNK * BSTRIDE)          // 18432 B per split
#define SM_B 0                               // 2 bufs x 2 splits
#define SM_C (4 * BUF_SPLIT)                 // 73728: ||e||^2 table (4 KB)
#define SM_IDX (SM_C + 4096)                 // 77824: per-row argmin (1 KB)
#define SM_TOTAL (SM_IDX + ROWS_PER_CTA * 4) // 78848

// ---------------- device scratch ----------------
__device__ __half g_Ah[(size_t)NROWS * DIM];
__device__ __half g_Al[(size_t)NROWS * DIM];
__device__ __half g_Bh[KCODES * DIM];
__device__ __half g_Bl[KCODES * DIM];
__device__ float g_c[KCODES];

// ---------------- asm helpers ----------------
__device__ __forceinline__ uint32_t smem_u32(const void* p) {
    uint32_t a;
    asm("{ .reg .u64 t; cvta.to.shared.u64 t, %1; cvt.u32.u64 %0, t; }" : "=r"(a) : "l"(p));
    return a;
}
__device__ __forceinline__ void mma16816(float* d, const uint32_t* a, const uint32_t* b) {
    asm volatile(
        "mma.sync.aligned.m16n8k16.row.col.f32.f16.f16.f32 "
        "{%0,%1,%2,%3}, {%4,%5,%6,%7}, {%8,%9}, {%0,%1,%2,%3};"
        : "+f"(d[0]), "+f"(d[1]), "+f"(d[2]), "+f"(d[3])
        : "r"(a[0]), "r"(a[1]), "r"(a[2]), "r"(a[3]), "r"(b[0]), "r"(b[1]));
}
__device__ __forceinline__ void ldsm_x2(uint32_t& r0, uint32_t& r1, uint32_t addr) {
    asm volatile("ldmatrix.sync.aligned.m8n8.x2.shared.b16 {%0,%1}, [%2];"
                 : "=r"(r0), "=r"(r1) : "r"(addr));
}
#define CP_ASYNC16(dst, src) \
    asm volatile("cp.async.cg.shared.global [%0], [%1], 16;" :: "r"(dst), "l"(src))
#define CP_COMMIT() asm volatile("cp.async.commit_group;" ::: "memory")
#define CP_WAIT(N)  asm volatile("cp.async.wait_group %0;" :: "n"(N) : "memory")

// ---------------- prep kernels ----------------
__global__ void prep_codes(const float* __restrict__ emb) {
    int k = blockIdx.x * blockDim.x + threadIdx.x;
    if (k >= KCODES) return;
    float c = 0.f;
#pragma unroll 4
    for (int d = 0; d < DIM; d++) {
        float x = emb[k * DIM + d];
        c += x * x;
        float t = -2.0f * x;
        __half h = __float2half(t);
        __half l = __float2half(t - __half2float(h));
        g_Bh[k * DIM + d] = h;
        g_Bl[k * DIM + d] = l;
    }
    g_c[k] = c;
}

__global__ void prep_inputs(const float* __restrict__ in) {
    size_t i = (size_t)blockIdx.x * blockDim.x + threadIdx.x;  // one float4
    float4 v = ((const float4*)in)[i];
    float xs[4] = {v.x, v.y, v.z, v.w};
    __half hs[4], ls[4];
#pragma unroll
    for (int j = 0; j < 4; j++) {
        __half h = __float2half(xs[j]);
        hs[j] = h;
        ls[j] = __float2half(xs[j] - __half2float(h));
    }
    ((__half2*)g_Ah)[2 * i]     = __halves2half2(hs[0], hs[1]);
    ((__half2*)g_Ah)[2 * i + 1] = __halves2half2(hs[2], hs[3]);
    ((__half2*)g_Al)[2 * i]     = __halves2half2(ls[0], ls[1]);
    ((__half2*)g_Al)[2 * i + 1] = __halves2half2(ls[2], ls[3]);
}

// ---------------- main kernel ----------------
__device__ __forceinline__ void issue_B_copy(char* smem, int chunk, int tid) {
    const int buf = chunk & 1;
    // 2 splits x 128 rows x 8 sixteen-byte segments = 2048 ops; 8 per thread
    const __half* srcs[2] = {g_Bh, g_Bl};
#pragma unroll
    for (int j = 0; j < 8; j++) {
        int op = j * THREADS + tid;          // 0..2047
        int s = op >> 10;                    // split
        int rowcol = op & 1023;              // row*8 + col16
        int row = rowcol >> 3;
        int col = rowcol & 7;
        uint32_t dst = smem_u32(smem + SM_B + (buf * 2 + s) * BUF_SPLIT
                                + row * BSTRIDE + col * 16);
        const char* src = (const char*)srcs[s]
                        + ((size_t)(chunk * CHUNK + row) * DIM + col * 8) * 2;
        CP_ASYNC16(dst, src);
    }
}

__global__ __launch_bounds__(THREADS, 2)
void vq_main(const float* __restrict__ inputs,
             const float* __restrict__ emb,
             float* __restrict__ out_q,
             float* __restrict__ out_idx,
             float* __restrict__ out_loss) {
    extern __shared__ __align__(16) char smem[];
    const int tid = threadIdx.x;
    const int wid = tid >> 5;
    const int lane = tid & 31;
    const int q = lane & 3;           // lane quad pos
    const int lr = lane >> 2;         // lane row (0..7)

    float* s_c = (float*)(smem + SM_C);
    int* s_idx = (int*)(smem + SM_IDX);

    // ||e||^2 table
#pragma unroll
    for (int i = tid; i < KCODES; i += THREADS) s_c[i] = g_c[i];

    // prefetch B chunk 0
    issue_B_copy(smem, 0, tid);
    CP_COMMIT();

    // A fragments in registers (2 splits x 2 mtiles x 4 ktiles x 4 regs)
    uint32_t ah[2][4][4], al[2][4][4];
    {
        const int row0 = blockIdx.x * ROWS_PER_CTA + wid * 32 + lr;
#pragma unroll
        for (int mt = 0; mt < 2; mt++) {
#pragma unroll
            for (int kt = 0; kt < 4; kt++) {
                size_t base = (size_t)(row0 + mt * 16) * DIM + kt * 16 + 2 * q;
                ah[mt][kt][0] = *(const uint32_t*)(g_Ah + base);
                ah[mt][kt][1] = *(const uint32_t*)(g_Ah + base + 8 * DIM);
                ah[mt][kt][2] = *(const uint32_t*)(g_Ah + base + 8);
                ah[mt][kt][3] = *(const uint32_t*)(g_Ah + base + 8 * DIM + 8);
                al[mt][kt][0] = *(const uint32_t*)(g_Al + base);
                al[mt][kt][1] = *(const uint32_t*)(g_Al + base + 8 * DIM);
                al[mt][kt][2] = *(const uint32_t*)(g_Al + base + 8);
                al[mt][kt][3] = *(const uint32_t*)(g_Al + base + 8 * DIM + 8);
            }
        }
    }

    float best[4] = {3.4e38f, 3.4e38f, 3.4e38f, 3.4e38f};
    int bidx[4] = {0, 0, 0, 0};

    for (int c = 0; c < NCHUNK; c++) {
        if (c + 1 < NCHUNK) {
            issue_B_copy(smem, c + 1, tid);
            CP_COMMIT();
            CP_WAIT(1);
        } else {
            CP_WAIT(0);
        }
        __syncthreads();

        const int buf = c & 1;
        const uint32_t bh_base = smem_u32(smem + SM_B + (buf * 2 + 0) * BUF_SPLIT);
        const uint32_t bl_base = smem_u32(smem + SM_B + (buf * 2 + 1) * BUF_SPLIT);
        // ldmatrix row address pieces for this lane
        const uint32_t lrow = (lane & 7) * BSTRIDE + ((lane >> 3) & 1) * 16;

#pragma unroll 4
        for (int nt = 0; nt < CHUNK / 8; nt++) {
            uint32_t bh[4][2], bl[4][2];
#pragma unroll
            for (int kt = 0; kt < 4; kt++) {
                uint32_t off = nt * 8 * BSTRIDE + kt * 32 + lrow;
                ldsm_x2(bh[kt][0], bh[kt][1], bh_base + off);
                ldsm_x2(bl[kt][0], bl[kt][1], bl_base + off);
            }
            float acc[2][4] = {{0.f, 0.f, 0.f, 0.f}, {0.f, 0.f, 0.f, 0.f}};
#pragma unroll
            for (int mt = 0; mt < 2; mt++) {
#pragma unroll
                for (int kt = 0; kt < 4; kt++) mma16816(acc[mt], ah[mt][kt], bh[kt]);
#pragma unroll
                for (int kt = 0; kt < 4; kt++) mma16816(acc[mt], al[mt][kt], bh[kt]);
#pragma unroll
                for (int kt = 0; kt < 4; kt++) mma16816(acc[mt], ah[mt][kt], bl[kt]);
#pragma unroll
                for (int kt = 0; kt < 4; kt++) mma16816(acc[mt], al[mt][kt], bl[kt]);
            }
            // argmin update: thread covers codes kb+2q, kb+2q+1 for 4 row slots
            const int kb = c * CHUNK + nt * 8;
            const float c0 = s_c[kb + 2 * q];
            const float c1 = s_c[kb + 2 * q + 1];
#pragma unroll
            for (int mt = 0; mt < 2; mt++) {
#pragma unroll
                for (int half = 0; half < 2; half++) {
                    const int slot = mt * 2 + half;
                    float s0 = acc[mt][half * 2 + 0] + c0;
                    float s1 = acc[mt][half * 2 + 1] + c1;
                    if (s0 < best[slot]) { best[slot] = s0; bidx[slot] = kb + 2 * q; }
                    if (s1 < best[slot]) { best[slot] = s1; bidx[slot] = kb + 2 * q + 1; }
                }
            }
        }
        __syncthreads();
    }

    // reduce argmin across the 4 lanes of each quad-row
#pragma unroll
    for (int off = 1; off <= 2; off <<= 1) {
#pragma unroll
        for (int s = 0; s < 4; s++) {
            float ob = __shfl_xor_sync(0xffffffffu, best[s], off);
            int oi = __shfl_xor_sync(0xffffffffu, bidx[s], off);
            if (ob < best[s] || (ob == best[s] && oi < bidx[s])) {
                best[s] = ob; bidx[s] = oi;
            }
        }
    }
    if (q == 0) {
        const int rbase = wid * 32 + lr;
#pragma unroll
        for (int s = 0; s < 4; s++) s_idx[rbase + s * 8] = bidx[s];
    }
    __syncthreads();

    // exact straight-through epilogue, one row per thread
    {
        const int row = blockIdx.x * ROWS_PER_CTA + tid;
        const int widx = s_idx[tid];
        const float4* e4 = (const float4*)(emb + (size_t)widx * DIM);
        const float4* x4 = (const float4*)(inputs + (size_t)row * DIM);
        float4* o4 = (float4*)(out_q + (size_t)row * DIM);
        float loss = 0.f;
#pragma unroll
        for (int j = 0; j < 16; j++) {
            float4 xv = x4[j];
            float4 ev = e4[j];
            float dx = ev.x - xv.x, dy = ev.y - xv.y;
            float dz = ev.z - xv.z, dw = ev.w - xv.w;
            loss += dx * dx + dy * dy + dz * dz + dw * dw;
            o4[j] = make_float4(xv.x + dx, xv.y + dy, xv.z + dz, xv.w + dw);
        }
        out_idx[row] = (float)widx;
        out_loss[row] = 1.25f * loss;
    }
}

// ---------------- launcher ----------------
extern "C" void kernel_launch(void* const* d_in, const int* in_sizes, int n_in,
                              void* d_out, int out_size) {
    const float* inputs = (const float*)d_in[0];
    const float* emb = (const float*)d_in[1];
    float* out = (float*)d_out;

    float* out_q = out;
    float* out_idx = out + (size_t)NROWS * DIM;
    float* out_loss = out_idx + NROWS;

    static bool attr_set = false;
    if (!attr_set) {
        cudaFuncSetAttribute(vq_main, cudaFuncAttributeMaxDynamicSharedMemorySize, SM_TOTAL);
        attr_set = true;
    }

    prep_codes<<<(KCODES + 127) / 128, 128>>>(emb);
    prep_inputs<<<((size_t)NROWS * DIM / 4) / 256, 256>>>(inputs);
    vq_main<<<NROWS / ROWS_PER_CTA, THREADS, SM_TOTAL>>>(inputs, emb, out_q, out_idx, out_loss);
}

// round 4
// speedup vs baseline: 2.5850x; 1.0059x over previous
#include <cuda_runtime.h>
#include <cuda_fp16.h>
#include <cstdint>

// VQ argmin via HMMA (mma.sync m16n8k16 f16->f32) with exact 2-way fp16 split.
// score(row,k) = ||e_k||^2 + dot(x_row, -2*e_k); x and -2e each split as h + l
// (fp16); all 4 products (hh,lh,hl,ll) accumulated in fp32 => fp32-class error.

#define DIM 64
#define KCODES 1024
#define NROWS (256*512)
#define ROWS_PER_CTA 256
#define THREADS 256
#define NWARP 8
#define CHUNK 128
#define NCHUNK (KCODES / CHUNK)

// B smem rows padded to 72 halves (144 B) -> conflict-free ldmatrix
#define BSTRIDE 144
#define BUF_SPLIT (CHUNK * BSTRIDE)          // 18432 B per split
#define SM_B 0                               // 2 bufs x 2 splits
#define SM_C (4 * BUF_SPLIT)                 // 73728: ||e||^2 table (4 KB)
#define SM_IDX (SM_C + 4096)                 // 77824: per-row argmin (1 KB)
#define SM_TOTAL (SM_IDX + ROWS_PER_CTA * 4) // 78848

// ---------------- device scratch ----------------
__device__ __half g_Ah[(size_t)NROWS * DIM];
__device__ __half g_Al[(size_t)NROWS * DIM];
__device__ __half g_Bh[KCODES * DIM];
__device__ __half g_Bl[KCODES * DIM];
__device__ float g_c[KCODES];

// ---------------- asm helpers ----------------
__device__ __forceinline__ uint32_t smem_u32(const void* p) {
    uint32_t a;
    asm("{ .reg .u64 t; cvta.to.shared.u64 t, %1; cvt.u32.u64 %0, t; }" : "=r"(a) : "l"(p));
    return a;
}
__device__ __forceinline__ void mma16816(float* d, const uint32_t* a, const uint32_t* b) {
    asm volatile(
        "mma.sync.aligned.m16n8k16.row.col.f32.f16.f16.f32 "
        "{%0,%1,%2,%3}, {%4,%5,%6,%7}, {%8,%9}, {%0,%1,%2,%3};"
        : "+f"(d[0]), "+f"(d[1]), "+f"(d[2]), "+f"(d[3])
        : "r"(a[0]), "r"(a[1]), "r"(a[2]), "r"(a[3]), "r"(b[0]), "r"(b[1]));
}
__device__ __forceinline__ void ldsm_x2(uint32_t& r0, uint32_t& r1, uint32_t addr) {
    asm volatile("ldmatrix.sync.aligned.m8n8.x2.shared.b16 {%0,%1}, [%2];"
                 : "=r"(r0), "=r"(r1) : "r"(addr));
}
#define CP_ASYNC16(dst, src) \
    asm volatile("cp.async.cg.shared.global [%0], [%1], 16;" :: "r"(dst), "l"(src))
#define CP_COMMIT() asm volatile("cp.async.commit_group;" ::: "memory")
#define CP_WAIT(N)  asm volatile("cp.async.wait_group %0;" :: "n"(N) : "memory")

// ---------------- prep kernels ----------------
__global__ void prep_codes(const float* __restrict__ emb) {
    int k = blockIdx.x * blockDim.x + threadIdx.x;
    if (k >= KCODES) return;
    float c = 0.f;
#pragma unroll 4
    for (int d = 0; d < DIM; d++) {
        float x = emb[k * DIM + d];
        c += x * x;
        float t = -2.0f * x;
        __half h = __float2half(t);
        __half l = __float2half(t - __half2float(h));
        g_Bh[k * DIM + d] = h;
        g_Bl[k * DIM + d] = l;
    }
    g_c[k] = c;
}

__global__ void prep_inputs(const float* __restrict__ in) {
    size_t i = (size_t)blockIdx.x * blockDim.x + threadIdx.x;  // one float4
    float4 v = ((const float4*)in)[i];
    float xs[4] = {v.x, v.y, v.z, v.w};
    __half hs[4], ls[4];
#pragma unroll
    for (int j = 0; j < 4; j++) {
        __half h = __float2half(xs[j]);
        hs[j] = h;
        ls[j] = __float2half(xs[j] - __half2float(h));
    }
    ((__half2*)g_Ah)[2 * i]     = __halves2half2(hs[0], hs[1]);
    ((__half2*)g_Ah)[2 * i + 1] = __halves2half2(hs[2], hs[3]);
    ((__half2*)g_Al)[2 * i]     = __halves2half2(ls[0], ls[1]);
    ((__half2*)g_Al)[2 * i + 1] = __halves2half2(ls[2], ls[3]);
}

// ---------------- main kernel ----------------
__device__ __forceinline__ void issue_B_copy(char* smem, int chunk, int tid) {
    const int buf = chunk & 1;
    // 2 splits x 128 rows x 8 sixteen-byte segments = 2048 ops; 8 per thread
    const __half* srcs[2] = {g_Bh, g_Bl};
#pragma unroll
    for (int j = 0; j < 8; j++) {
        int op = j * THREADS + tid;          // 0..2047
        int s = op >> 10;                    // split
        int rowcol = op & 1023;              // row*8 + col16
        int row = rowcol >> 3;
        int col = rowcol & 7;
        uint32_t dst = smem_u32(smem + SM_B + (buf * 2 + s) * BUF_SPLIT
                                + row * BSTRIDE + col * 16);
        const char* src = (const char*)srcs[s]
                        + ((size_t)(chunk * CHUNK + row) * DIM + col * 8) * 2;
        CP_ASYNC16(dst, src);
    }
}

__global__ __launch_bounds__(THREADS, 2)
void vq_main(const float* __restrict__ inputs,
             const float* __restrict__ emb,
             float* __restrict__ out_q,
             float* __restrict__ out_idx,
             float* __restrict__ out_loss) {
    extern __shared__ __align__(16) char smem[];
    const int tid = threadIdx.x;
    const int wid = tid >> 5;
    const int lane = tid & 31;
    const int q = lane & 3;           // lane quad pos
    const int lr = lane >> 2;         // lane row (0..7)

    float* s_c = (float*)(smem + SM_C);
    int* s_idx = (int*)(smem + SM_IDX);

    // ||e||^2 table
#pragma unroll
    for (int i = tid; i < KCODES; i += THREADS) s_c[i] = g_c[i];

    // prefetch B chunk 0
    issue_B_copy(smem, 0, tid);
    CP_COMMIT();

    // A fragments in registers (2 splits x 2 mtiles x 4 ktiles x 4 regs)
    uint32_t ah[2][4][4], al[2][4][4];
    {
        const int row0 = blockIdx.x * ROWS_PER_CTA + wid * 32 + lr;
#pragma unroll
        for (int mt = 0; mt < 2; mt++) {
#pragma unroll
            for (int kt = 0; kt < 4; kt++) {
                size_t base = (size_t)(row0 + mt * 16) * DIM + kt * 16 + 2 * q;
                ah[mt][kt][0] = *(const uint32_t*)(g_Ah + base);
                ah[mt][kt][1] = *(const uint32_t*)(g_Ah + base + 8 * DIM);
                ah[mt][kt][2] = *(const uint32_t*)(g_Ah + base + 8);
                ah[mt][kt][3] = *(const uint32_t*)(g_Ah + base + 8 * DIM + 8);
                al[mt][kt][0] = *(const uint32_t*)(g_Al + base);
                al[mt][kt][1] = *(const uint32_t*)(g_Al + base + 8 * DIM);
                al[mt][kt][2] = *(const uint32_t*)(g_Al + base + 8);
                al[mt][kt][3] = *(const uint32_t*)(g_Al + base + 8 * DIM + 8);
            }
        }
    }

    float best[4] = {3.4e38f, 3.4e38f, 3.4e38f, 3.4e38f};
    int bidx[4] = {0, 0, 0, 0};

    for (int c = 0; c < NCHUNK; c++) {
        if (c + 1 < NCHUNK) {
            issue_B_copy(smem, c + 1, tid);
            CP_COMMIT();
            CP_WAIT(1);
        } else {
            CP_WAIT(0);
        }
        __syncthreads();

        const int buf = c & 1;
        const uint32_t bh_base = smem_u32(smem + SM_B + (buf * 2 + 0) * BUF_SPLIT);
        const uint32_t bl_base = smem_u32(smem + SM_B + (buf * 2 + 1) * BUF_SPLIT);
        // ldmatrix row address pieces for this lane
        const uint32_t lrow = (lane & 7) * BSTRIDE + ((lane >> 3) & 1) * 16;

#pragma unroll 4
        for (int nt = 0; nt < CHUNK / 8; nt++) {
            uint32_t bh[4][2], bl[4][2];
#pragma unroll
            for (int kt = 0; kt < 4; kt++) {
                uint32_t off = nt * 8 * BSTRIDE + kt * 32 + lrow;
                ldsm_x2(bh[kt][0], bh[kt][1], bh_base + off);
                ldsm_x2(bl[kt][0], bl[kt][1], bl_base + off);
            }
            float acc[2][4] = {{0.f, 0.f, 0.f, 0.f}, {0.f, 0.f, 0.f, 0.f}};
#pragma unroll
            for (int mt = 0; mt < 2; mt++) {
#pragma unroll
                for (int kt = 0; kt < 4; kt++) mma16816(acc[mt], ah[mt][kt], bh[kt]);
#pragma unroll
                for (int kt = 0; kt < 4; kt++) mma16816(acc[mt], al[mt][kt], bh[kt]);
#pragma unroll
                for (int kt = 0; kt < 4; kt++) mma16816(acc[mt], ah[mt][kt], bl[kt]);
#pragma unroll
                for (int kt = 0; kt < 4; kt++) mma16816(acc[mt], al[mt][kt], bl[kt]);
            }
            // argmin update: thread covers codes kb+2q, kb+2q+1 for 4 row slots
            const int kb = c * CHUNK + nt * 8;
            const float c0 = s_c[kb + 2 * q];
            const float c1 = s_c[kb + 2 * q + 1];
#pragma unroll
            for (int mt = 0; mt < 2; mt++) {
#pragma unroll
                for (int half = 0; half < 2; half++) {
                    const int slot = mt * 2 + half;
                    float s0 = acc[mt][half * 2 + 0] + c0;
                    float s1 = acc[mt][half * 2 + 1] + c1;
                    if (s0 < best[slot]) { best[slot] = s0; bidx[slot] = kb + 2 * q; }
                    if (s1 < best[slot]) { best[slot] = s1; bidx[slot] = kb + 2 * q + 1; }
                }
            }
        }
        __syncthreads();
    }

    // reduce argmin across the 4 lanes of each quad-row
#pragma unroll
    for (int off = 1; off <= 2; off <<= 1) {
#pragma unroll
        for (int s = 0; s < 4; s++) {
            float ob = __shfl_xor_sync(0xffffffffu, best[s], off);
            int oi = __shfl_xor_sync(0xffffffffu, bidx[s], off);
            if (ob < best[s] || (ob == best[s] && oi < bidx[s])) {
                best[s] = ob; bidx[s] = oi;
            }
        }
    }
    if (q == 0) {
        const int rbase = wid * 32 + lr;
#pragma unroll
        for (int s = 0; s < 4; s++) s_idx[rbase + s * 8] = bidx[s];
    }
    __syncthreads();

    // exact straight-through epilogue, one row per thread
    {
        const int row = blockIdx.x * ROWS_PER_CTA + tid;
        const int widx = s_idx[tid];
        const float4* e4 = (const float4*)(emb + (size_t)widx * DIM);
        const float4* x4 = (const float4*)(inputs + (size_t)row * DIM);
        float4* o4 = (float4*)(out_q + (size_t)row * DIM);
        float loss = 0.f;
#pragma unroll
        for (int j = 0; j < 16; j++) {
            float4 xv = x4[j];
            float4 ev = e4[j];
            float dx = ev.x - xv.x, dy = ev.y - xv.y;
            float dz = ev.z - xv.z, dw = ev.w - xv.w;
            loss += dx * dx + dy * dy + dz * dz + dw * dw;
            o4[j] = make_float4(xv.x + dx, xv.y + dy, xv.z + dz, xv.w + dw);
        }
        out_idx[row] = (float)widx;
        out_loss[row] = 1.25f * loss;
    }
}

// ---------------- launcher ----------------
extern "C" void kernel_launch(void* const* d_in, const int* in_sizes, int n_in,
                              void* d_out, int out_size) {
    const float* inputs = (const float*)d_in[0];
    const float* emb = (const float*)d_in[1];
    float* out = (float*)d_out;

    float* out_q = out;
    float* out_idx = out + (size_t)NROWS * DIM;
    float* out_loss = out_idx + NROWS;

    static bool attr_set = false;
    if (!attr_set) {
        cudaFuncSetAttribute(vq_main, cudaFuncAttributeMaxDynamicSharedMemorySize, SM_TOTAL);
        attr_set = true;
    }

    prep_codes<<<(KCODES + 127) / 128, 128>>>(emb);
    prep_inputs<<<((size_t)NROWS * DIM / 4) / 256, 256>>>(inputs);
    vq_main<<<NROWS / ROWS_PER_CTA, THREADS, SM_TOTAL>>>(inputs, emb, out_q, out_idx, out_loss);
}

// round 5
// speedup vs baseline: 2.9888x; 1.1562x over previous
#include <cuda_runtime.h>
#include <cuda_fp16.h>
#include <cstdint>

// VQ argmin via HMMA (mma.sync m16n8k16 f16->f32), exact 2-way fp16 split.
// score(row,k) = ||e_k||^2 + dot(x_row, -2*e_k); 4 products (hh,lh,hl,ll), fp32 acc.
// A (inputs) converted to fragments in-kernel; B (-2e splits) via fast prep kernel.

#define DIM 64
#define KCODES 1024
#define NROWS (256*512)
#define ROWS_PER_CTA 256
#define THREADS 256
#define CHUNK 128
#define NCHUNK (KCODES / CHUNK)

// B smem rows padded to 72 halves (144 B) -> conflict-free ldmatrix
#define BSTRIDE 144
#define BUF_SPLIT (CHUNK * BSTRIDE)          // 18432 B per split
#define SM_B 0                               // 2 bufs x 2 splits
#define SM_C (4 * BUF_SPLIT)                 // 73728: ||e||^2 table (4 KB)
#define SM_IDX (SM_C + 4096)                 // 77824: per-row argmin (1 KB)
#define SM_TOTAL (SM_IDX + ROWS_PER_CTA * 4) // 78848

// ---------------- device scratch ----------------
__device__ __half g_Bh[KCODES * DIM];
__device__ __half g_Bl[KCODES * DIM];
__device__ float g_c[KCODES];

// ---------------- asm helpers ----------------
__device__ __forceinline__ uint32_t smem_u32(const void* p) {
    uint32_t a;
    asm("{ .reg .u64 t; cvta.to.shared.u64 t, %1; cvt.u32.u64 %0, t; }" : "=r"(a) : "l"(p));
    return a;
}
__device__ __forceinline__ void mma16816(float* d, const uint32_t* a, const uint32_t* b) {
    asm volatile(
        "mma.sync.aligned.m16n8k16.row.col.f32.f16.f16.f32 "
        "{%0,%1,%2,%3}, {%4,%5,%6,%7}, {%8,%9}, {%0,%1,%2,%3};"
        : "+f"(d[0]), "+f"(d[1]), "+f"(d[2]), "+f"(d[3])
        : "r"(a[0]), "r"(a[1]), "r"(a[2]), "r"(a[3]), "r"(b[0]), "r"(b[1]));
}
__device__ __forceinline__ void ldsm_x4(uint32_t* r, uint32_t addr) {
    asm volatile("ldmatrix.sync.aligned.m8n8.x4.shared.b16 {%0,%1,%2,%3}, [%4];"
                 : "=r"(r[0]), "=r"(r[1]), "=r"(r[2]), "=r"(r[3]) : "r"(addr));
}
#define CP_ASYNC16(dst, src) \
    asm volatile("cp.async.cg.shared.global [%0], [%1], 16;" :: "r"(dst), "l"(src))
#define CP_COMMIT() asm volatile("cp.async.commit_group;" ::: "memory")
#define CP_WAIT(N)  asm volatile("cp.async.wait_group %0;" :: "n"(N) : "memory")

__device__ __forceinline__ void splitf2(float2 v, uint32_t& hh, uint32_t& ll) {
    __half hx = __float2half_rn(v.x);
    __half hy = __float2half_rn(v.y);
    __half lx = __float2half_rn(v.x - __half2float(hx));
    __half ly = __float2half_rn(v.y - __half2float(hy));
    __half2 H = __halves2half2(hx, hy);
    __half2 L = __halves2half2(lx, ly);
    hh = *(uint32_t*)&H;
    ll = *(uint32_t*)&L;
}

// ---------------- prep kernel (codes): coalesced, warp = 2 codes ----------------
__global__ void prep_codes(const float* __restrict__ emb) {
    const int wid = threadIdx.x >> 5;
    const int lane = threadIdx.x & 31;
    const int code = blockIdx.x * 8 + wid * 2 + (lane >> 4);
    const int seg = lane & 15;                       // float4 slot within code row
    float4 v = ((const float4*)(emb + (size_t)code * DIM))[seg];
    float c = v.x * v.x + v.y * v.y + v.z * v.z + v.w * v.w;
#pragma unroll
    for (int off = 8; off; off >>= 1) c += __shfl_down_sync(0xffffffffu, c, off, 16);
    if (seg == 0) g_c[code] = c;

    float t[4] = {-2.f * v.x, -2.f * v.y, -2.f * v.z, -2.f * v.w};
    uint32_t h01, l01, h23, l23;
    splitf2(make_float2(t[0], t[1]), h01, l01);
    splitf2(make_float2(t[2], t[3]), h23, l23);
    uint32_t* bh = (uint32_t*)(g_Bh + (size_t)code * DIM) + seg * 2;
    uint32_t* bl = (uint32_t*)(g_Bl + (size_t)code * DIM) + seg * 2;
    bh[0] = h01; bh[1] = h23;
    bl[0] = l01; bl[1] = l23;
}

// ---------------- main kernel ----------------
__device__ __forceinline__ void issue_B_copy(char* smem, int chunk, int tid) {
    const int buf = chunk & 1;
    const __half* srcs[2] = {g_Bh, g_Bl};
#pragma unroll
    for (int j = 0; j < 8; j++) {
        int op = j * THREADS + tid;          // 0..2047
        int s = op >> 10;                    // split
        int rowcol = op & 1023;              // row*8 + col16
        int row = rowcol >> 3;
        int col = rowcol & 7;
        uint32_t dst = smem_u32(smem + SM_B + (buf * 2 + s) * BUF_SPLIT
                                + row * BSTRIDE + col * 16);
        const char* src = (const char*)srcs[s]
                        + ((size_t)(chunk * CHUNK + row) * DIM + col * 8) * 2;
        CP_ASYNC16(dst, src);
    }
}

__global__ __launch_bounds__(THREADS, 2)
void vq_main(const float* __restrict__ inputs,
             const float* __restrict__ emb,
             float* __restrict__ out_q,
             float* __restrict__ out_idx,
             float* __restrict__ out_loss) {
    extern __shared__ __align__(16) char smem[];
    const int tid = threadIdx.x;
    const int wid = tid >> 5;
    const int lane = tid & 31;
    const int q = lane & 3;           // lane quad pos
    const int lr = lane >> 2;         // lane row (0..7)

    float* s_c = (float*)(smem + SM_C);
    int* s_idx = (int*)(smem + SM_IDX);

#pragma unroll
    for (int i = tid; i < KCODES; i += THREADS) s_c[i] = g_c[i];

    // prefetch B chunk 0
    issue_B_copy(smem, 0, tid);
    CP_COMMIT();

    // A fragments from fp32 inputs, converted in registers
    uint32_t ah[2][4][4], al[2][4][4];
    {
        const int row0 = blockIdx.x * ROWS_PER_CTA + wid * 32 + lr;
#pragma unroll
        for (int mt = 0; mt < 2; mt++) {
#pragma unroll
            for (int kt = 0; kt < 4; kt++) {
                size_t base = (size_t)(row0 + mt * 16) * DIM + kt * 16 + 2 * q;
                splitf2(*(const float2*)(inputs + base),               ah[mt][kt][0], al[mt][kt][0]);
                splitf2(*(const float2*)(inputs + base + 8 * DIM),     ah[mt][kt][1], al[mt][kt][1]);
                splitf2(*(const float2*)(inputs + base + 8),           ah[mt][kt][2], al[mt][kt][2]);
                splitf2(*(const float2*)(inputs + base + 8 * DIM + 8), ah[mt][kt][3], al[mt][kt][3]);
            }
        }
    }

    float best[4] = {3.4e38f, 3.4e38f, 3.4e38f, 3.4e38f};
    int bidx[4] = {0, 0, 0, 0};

    // ldmatrix.x4 lane address: matrix = lane>>3 -> {nt-half, k-chunk}
    const uint32_t lbase = ((((lane >> 4) & 1) * 8 + (lane & 7)) * BSTRIDE)
                         + ((lane >> 3) & 1) * 16;

    for (int c = 0; c < NCHUNK; c++) {
        if (c + 1 < NCHUNK) {
            issue_B_copy(smem, c + 1, tid);
            CP_COMMIT();
            CP_WAIT(1);
        } else {
            CP_WAIT(0);
        }
        __syncthreads();

        const int buf = c & 1;
        const uint32_t bh_base = smem_u32(smem + SM_B + (buf * 2 + 0) * BUF_SPLIT) + lbase;
        const uint32_t bl_base = smem_u32(smem + SM_B + (buf * 2 + 1) * BUF_SPLIT) + lbase;

#pragma unroll 2
        for (int ntp = 0; ntp < CHUNK / 16; ntp++) {   // pair of n-tiles
            const uint32_t poff = ntp * 16 * BSTRIDE;
            uint32_t bf[4][4];
            float acc[2][2][4] = {};                   // [half][mt][4]

            // h-split of B: hh + lh products
#pragma unroll
            for (int kt = 0; kt < 4; kt++) ldsm_x4(bf[kt], bh_base + poff + kt * 32);
#pragma unroll
            for (int half = 0; half < 2; half++)
#pragma unroll
                for (int mt = 0; mt < 2; mt++) {
#pragma unroll
                    for (int kt = 0; kt < 4; kt++) mma16816(acc[half][mt], ah[mt][kt], &bf[kt][2 * half]);
#pragma unroll
                    for (int kt = 0; kt < 4; kt++) mma16816(acc[half][mt], al[mt][kt], &bf[kt][2 * half]);
                }
            // l-split of B: hl + ll products (reuse bf regs)
#pragma unroll
            for (int kt = 0; kt < 4; kt++) ldsm_x4(bf[kt], bl_base + poff + kt * 32);
#pragma unroll
            for (int half = 0; half < 2; half++)
#pragma unroll
                for (int mt = 0; mt < 2; mt++) {
#pragma unroll
                    for (int kt = 0; kt < 4; kt++) mma16816(acc[half][mt], ah[mt][kt], &bf[kt][2 * half]);
#pragma unroll
                    for (int kt = 0; kt < 4; kt++) mma16816(acc[half][mt], al[mt][kt], &bf[kt][2 * half]);
                }

            // argmin update for both n-tiles of the pair
#pragma unroll
            for (int half = 0; half < 2; half++) {
                const int kb = c * CHUNK + (ntp * 2 + half) * 8;
                const float c0 = s_c[kb + 2 * q];
                const float c1 = s_c[kb + 2 * q + 1];
#pragma unroll
                for (int mt = 0; mt < 2; mt++) {
#pragma unroll
                    for (int h2 = 0; h2 < 2; h2++) {
                        const int slot = mt * 2 + h2;
                        float s0 = acc[half][mt][h2 * 2 + 0] + c0;
                        float s1 = acc[half][mt][h2 * 2 + 1] + c1;
                        if (s0 < best[slot]) { best[slot] = s0; bidx[slot] = kb + 2 * q; }
                        if (s1 < best[slot]) { best[slot] = s1; bidx[slot] = kb + 2 * q + 1; }
                    }
                }
            }
        }
        __syncthreads();
    }

    // reduce argmin across the 4 lanes of each quad-row
#pragma unroll
    for (int off = 1; off <= 2; off <<= 1) {
#pragma unroll
        for (int s = 0; s < 4; s++) {
            float ob = __shfl_xor_sync(0xffffffffu, best[s], off);
            int oi = __shfl_xor_sync(0xffffffffu, bidx[s], off);
            if (ob < best[s] || (ob == best[s] && oi < bidx[s])) {
                best[s] = ob; bidx[s] = oi;
            }
        }
    }
    if (q == 0) {
        const int rbase = wid * 32 + lr;
#pragma unroll
        for (int s = 0; s < 4; s++) s_idx[rbase + s * 8] = bidx[s];
    }
    __syncthreads();

    // exact straight-through epilogue, one row per thread
    {
        const int row = blockIdx.x * ROWS_PER_CTA + tid;
        const int widx = s_idx[tid];
        const float4* e4 = (const float4*)(emb + (size_t)widx * DIM);
        const float4* x4 = (const float4*)(inputs + (size_t)row * DIM);
        float4* o4 = (float4*)(out_q + (size_t)row * DIM);
        float loss = 0.f;
#pragma unroll
        for (int j = 0; j < 16; j++) {
            float4 xv = x4[j];
            float4 ev = e4[j];
            float dx = ev.x - xv.x, dy = ev.y - xv.y;
            float dz = ev.z - xv.z, dw = ev.w - xv.w;
            loss += dx * dx + dy * dy + dz * dz + dw * dw;
            o4[j] = make_float4(xv.x + dx, xv.y + dy, xv.z + dz, xv.w + dw);
        }
        out_idx[row] = (float)widx;
        out_loss[row] = 1.25f * loss;
    }
}

// ---------------- launcher ----------------
extern "C" void kernel_launch(void* const* d_in, const int* in_sizes, int n_in,
                              void* d_out, int out_size) {
    const float* inputs = (const float*)d_in[0];
    const float* emb = (const float*)d_in[1];
    float* out = (float*)d_out;

    float* out_q = out;
    float* out_idx = out + (size_t)NROWS * DIM;
    float* out_loss = out_idx + NROWS;

    static bool attr_set = false;
    if (!attr_set) {
        cudaFuncSetAttribute(vq_main, cudaFuncAttributeMaxDynamicSharedMemorySize, SM_TOTAL);
        attr_set = true;
    }

    prep_codes<<<KCODES / 8, 128>>>(emb);
    vq_main<<<NROWS / ROWS_PER_CTA, THREADS, SM_TOTAL>>>(inputs, emb, out_q, out_idx, out_loss);
}

// round 6
// speedup vs baseline: 3.5607x; 1.1913x over previous
#include <cuda_runtime.h>
#include <cuda_fp16.h>
#include <cstdint>

// VQ argmin via HMMA (mma.sync m16n8k16 f16->f32), 2-way fp16 split, 3 products
// (hh, lh, hl; ll dropped -- adds ~1.5e-5 rms score noise, same class as the
// fp32-accumulation rounding already present; argmin gaps are >>1e-4).

#define DIM 64
#define KCODES 1024
#define NROWS (256*512)
#define ROWS_PER_CTA 256
#define THREADS 256
#define CHUNK 128
#define NCHUNK (KCODES / CHUNK)

// B smem rows padded to 72 halves (144 B) -> conflict-free ldmatrix
#define BSTRIDE 144
#define BUF_SPLIT (CHUNK * BSTRIDE)          // 18432 B per split
#define SM_B 0                               // 2 bufs x 2 splits
#define SM_C (4 * BUF_SPLIT)                 // 73728: ||e||^2 table (4 KB)
#define SM_IDX (SM_C + 4096)                 // 77824: per-row argmin (1 KB)
#define SM_TOTAL (SM_IDX + ROWS_PER_CTA * 4) // 78848

// ---------------- device scratch ----------------
__device__ __half g_Bh[KCODES * DIM];
__device__ __half g_Bl[KCODES * DIM];
__device__ float g_c[KCODES];

// ---------------- asm helpers ----------------
__device__ __forceinline__ uint32_t smem_u32(const void* p) {
    uint32_t a;
    asm("{ .reg .u64 t; cvta.to.shared.u64 t, %1; cvt.u32.u64 %0, t; }" : "=r"(a) : "l"(p));
    return a;
}
__device__ __forceinline__ void mma16816(float* d, const uint32_t* a, const uint32_t* b) {
    asm volatile(
        "mma.sync.aligned.m16n8k16.row.col.f32.f16.f16.f32 "
        "{%0,%1,%2,%3}, {%4,%5,%6,%7}, {%8,%9}, {%0,%1,%2,%3};"
        : "+f"(d[0]), "+f"(d[1]), "+f"(d[2]), "+f"(d[3])
        : "r"(a[0]), "r"(a[1]), "r"(a[2]), "r"(a[3]), "r"(b[0]), "r"(b[1]));
}
__device__ __forceinline__ void ldsm_x4(uint32_t* r, uint32_t addr) {
    asm volatile("ldmatrix.sync.aligned.m8n8.x4.shared.b16 {%0,%1,%2,%3}, [%4];"
                 : "=r"(r[0]), "=r"(r[1]), "=r"(r[2]), "=r"(r[3]) : "r"(addr));
}
#define CP_ASYNC16(dst, src) \
    asm volatile("cp.async.cg.shared.global [%0], [%1], 16;" :: "r"(dst), "l"(src))
#define CP_COMMIT() asm volatile("cp.async.commit_group;" ::: "memory")
#define CP_WAIT(N)  asm volatile("cp.async.wait_group %0;" :: "n"(N) : "memory")

__device__ __forceinline__ void splitf2(float2 v, uint32_t& hh, uint32_t& ll) {
    __half hx = __float2half_rn(v.x);
    __half hy = __float2half_rn(v.y);
    __half lx = __float2half_rn(v.x - __half2float(hx));
    __half ly = __float2half_rn(v.y - __half2float(hy));
    __half2 H = __halves2half2(hx, hy);
    __half2 L = __halves2half2(lx, ly);
    hh = *(uint32_t*)&H;
    ll = *(uint32_t*)&L;
}

// ---------------- prep kernel (codes): coalesced, warp = 2 codes ----------------
__global__ void prep_codes(const float* __restrict__ emb) {
    const int wid = threadIdx.x >> 5;
    const int lane = threadIdx.x & 31;
    const int code = blockIdx.x * 8 + wid * 2 + (lane >> 4);
    const int seg = lane & 15;
    float4 v = ((const float4*)(emb + (size_t)code * DIM))[seg];
    float c = v.x * v.x + v.y * v.y + v.z * v.z + v.w * v.w;
#pragma unroll
    for (int off = 8; off; off >>= 1) c += __shfl_down_sync(0xffffffffu, c, off, 16);
    if (seg == 0) g_c[code] = c;

    float t[4] = {-2.f * v.x, -2.f * v.y, -2.f * v.z, -2.f * v.w};
    uint32_t h01, l01, h23, l23;
    splitf2(make_float2(t[0], t[1]), h01, l01);
    splitf2(make_float2(t[2], t[3]), h23, l23);
    uint32_t* bh = (uint32_t*)(g_Bh + (size_t)code * DIM) + seg * 2;
    uint32_t* bl = (uint32_t*)(g_Bl + (size_t)code * DIM) + seg * 2;
    bh[0] = h01; bh[1] = h23;
    bl[0] = l01; bl[1] = l23;
}

// ---------------- main kernel ----------------
__device__ __forceinline__ void issue_B_copy(char* smem, int chunk, int tid) {
    const int buf = chunk & 1;
    const __half* srcs[2] = {g_Bh, g_Bl};
#pragma unroll
    for (int j = 0; j < 8; j++) {
        int op = j * THREADS + tid;          // 0..2047
        int s = op >> 10;
        int rowcol = op & 1023;
        int row = rowcol >> 3;
        int col = rowcol & 7;
        uint32_t dst = smem_u32(smem + SM_B + (buf * 2 + s) * BUF_SPLIT
                                + row * BSTRIDE + col * 16);
        const char* src = (const char*)srcs[s]
                        + ((size_t)(chunk * CHUNK + row) * DIM + col * 8) * 2;
        CP_ASYNC16(dst, src);
    }
}

__global__ __launch_bounds__(THREADS, 2)
void vq_main(const float* __restrict__ inputs,
             const float* __restrict__ emb,
             float* __restrict__ out_q,
             float* __restrict__ out_idx,
             float* __restrict__ out_loss) {
    extern __shared__ __align__(16) char smem[];
    const int tid = threadIdx.x;
    const int wid = tid >> 5;
    const int lane = tid & 31;
    const int q = lane & 3;
    const int lr = lane >> 2;

    float* s_c = (float*)(smem + SM_C);
    int* s_idx = (int*)(smem + SM_IDX);

#pragma unroll
    for (int i = tid; i < KCODES; i += THREADS) s_c[i] = g_c[i];

    issue_B_copy(smem, 0, tid);
    CP_COMMIT();

    // A fragments from fp32 inputs, converted in registers
    uint32_t ah[2][4][4], al[2][4][4];
    {
        const int row0 = blockIdx.x * ROWS_PER_CTA + wid * 32 + lr;
#pragma unroll
        for (int mt = 0; mt < 2; mt++) {
#pragma unroll
            for (int kt = 0; kt < 4; kt++) {
                size_t base = (size_t)(row0 + mt * 16) * DIM + kt * 16 + 2 * q;
                splitf2(*(const float2*)(inputs + base),               ah[mt][kt][0], al[mt][kt][0]);
                splitf2(*(const float2*)(inputs + base + 8 * DIM),     ah[mt][kt][1], al[mt][kt][1]);
                splitf2(*(const float2*)(inputs + base + 8),           ah[mt][kt][2], al[mt][kt][2]);
                splitf2(*(const float2*)(inputs + base + 8 * DIM + 8), ah[mt][kt][3], al[mt][kt][3]);
            }
        }
    }

    float best[4] = {3.4e38f, 3.4e38f, 3.4e38f, 3.4e38f};
    int bidx[4] = {0, 0, 0, 0};

    const uint32_t lbase = ((((lane >> 4) & 1) * 8 + (lane & 7)) * BSTRIDE)
                         + ((lane >> 3) & 1) * 16;

    for (int c = 0; c < NCHUNK; c++) {
        if (c + 1 < NCHUNK) {
            issue_B_copy(smem, c + 1, tid);
            CP_COMMIT();
            CP_WAIT(1);
        } else {
            CP_WAIT(0);
        }
        __syncthreads();

        const int buf = c & 1;
        const uint32_t bh_base = smem_u32(smem + SM_B + (buf * 2 + 0) * BUF_SPLIT) + lbase;
        const uint32_t bl_base = smem_u32(smem + SM_B + (buf * 2 + 1) * BUF_SPLIT) + lbase;

#pragma unroll 2
        for (int ntp = 0; ntp < CHUNK / 16; ntp++) {   // pair of n-tiles
            const uint32_t poff = ntp * 16 * BSTRIDE;
            uint32_t bf[4][4];
            float acc[2][2][4] = {};                   // [half][mt][4]

            // b_h: hh + lh products
#pragma unroll
            for (int kt = 0; kt < 4; kt++) ldsm_x4(bf[kt], bh_base + poff + kt * 32);
#pragma unroll
            for (int half = 0; half < 2; half++)
#pragma unroll
                for (int mt = 0; mt < 2; mt++) {
#pragma unroll
                    for (int kt = 0; kt < 4; kt++) mma16816(acc[half][mt], ah[mt][kt], &bf[kt][2 * half]);
#pragma unroll
                    for (int kt = 0; kt < 4; kt++) mma16816(acc[half][mt], al[mt][kt], &bf[kt][2 * half]);
                }
            // b_l: hl product only (ll dropped)
#pragma unroll
            for (int kt = 0; kt < 4; kt++) ldsm_x4(bf[kt], bl_base + poff + kt * 32);
#pragma unroll
            for (int half = 0; half < 2; half++)
#pragma unroll
                for (int mt = 0; mt < 2; mt++)
#pragma unroll
                    for (int kt = 0; kt < 4; kt++) mma16816(acc[half][mt], ah[mt][kt], &bf[kt][2 * half]);

            // argmin update for both n-tiles of the pair
#pragma unroll
            for (int half = 0; half < 2; half++) {
                const int kb = c * CHUNK + (ntp * 2 + half) * 8;
                const float c0 = s_c[kb + 2 * q];
                const float c1 = s_c[kb + 2 * q + 1];
#pragma unroll
                for (int mt = 0; mt < 2; mt++) {
#pragma unroll
                    for (int h2 = 0; h2 < 2; h2++) {
                        const int slot = mt * 2 + h2;
                        float s0 = acc[half][mt][h2 * 2 + 0] + c0;
                        float s1 = acc[half][mt][h2 * 2 + 1] + c1;
                        if (s0 < best[slot]) { best[slot] = s0; bidx[slot] = kb + 2 * q; }
                        if (s1 < best[slot]) { best[slot] = s1; bidx[slot] = kb + 2 * q + 1; }
                    }
                }
            }
        }
        __syncthreads();
    }

    // reduce argmin across the 4 lanes of each quad-row
#pragma unroll
    for (int off = 1; off <= 2; off <<= 1) {
#pragma unroll
        for (int s = 0; s < 4; s++) {
            float ob = __shfl_xor_sync(0xffffffffu, best[s], off);
            int oi = __shfl_xor_sync(0xffffffffu, bidx[s], off);
            if (ob < best[s] || (ob == best[s] && oi < bidx[s])) {
                best[s] = ob; bidx[s] = oi;
            }
        }
    }
    if (q == 0) {
        const int rbase = wid * 32 + lr;
#pragma unroll
        for (int s = 0; s < 4; s++) s_idx[rbase + s * 8] = bidx[s];
    }
    __syncthreads();

    // exact straight-through epilogue, one row per thread
    {
        const int row = blockIdx.x * ROWS_PER_CTA + tid;
        const int widx = s_idx[tid];
        const float4* e4 = (const float4*)(emb + (size_t)widx * DIM);
        const float4* x4 = (const float4*)(inputs + (size_t)row * DIM);
        float4* o4 = (float4*)(out_q + (size_t)row * DIM);
        float loss = 0.f;
#pragma unroll
        for (int j = 0; j < 16; j++) {
            float4 xv = x4[j];
            float4 ev = e4[j];
            float dx = ev.x - xv.x, dy = ev.y - xv.y;
            float dz = ev.z - xv.z, dw = ev.w - xv.w;
            loss += dx * dx + dy * dy + dz * dz + dw * dw;
            o4[j] = make_float4(xv.x + dx, xv.y + dy, xv.z + dz, xv.w + dw);
        }
        out_idx[row] = (float)widx;
        out_loss[row] = 1.25f * loss;
    }
}

// ---------------- launcher ----------------
extern "C" void kernel_launch(void* const* d_in, const int* in_sizes, int n_in,
                              void* d_out, int out_size) {
    const float* inputs = (const float*)d_in[0];
    const float* emb = (const float*)d_in[1];
    float* out = (float*)d_out;

    float* out_q = out;
    float* out_idx = out + (size_t)NROWS * DIM;
    float* out_loss = out_idx + NROWS;

    static bool attr_set = false;
    if (!attr_set) {
        cudaFuncSetAttribute(vq_main, cudaFuncAttributeMaxDynamicSharedMemorySize, SM_TOTAL);
        attr_set = true;
    }

    prep_codes<<<KCODES / 8, 128>>>(emb);
    vq_main<<<NROWS / ROWS_PER_CTA, THREADS, SM_TOTAL>>>(inputs, emb, out_q, out_idx, out_loss);
}

// round 7
// speedup vs baseline: 3.7704x; 1.0589x over previous
#include <cuda_runtime.h>
#include <cuda_fp16.h>
#include <cstdint>

// VQ argmin via HMMA, 2-way fp16 split, 3 products (hh, lh, hl).
// Mixed-granularity scheduling: 296 full row-tiles + 216 tiles split into
// 3/4 + 1/4 code-range pieces (merged via exact u64 atomicMin keys) to beat
// wave quantization (makespan 2T -> ~1.75T on 296 CTA slots).

#define DIM 64
#define KCODES 1024
#define NROWS (256*512)
#define ROWS_PER_CTA 256
#define THREADS 256
#define CHUNK 128
#define NCHUNK (KCODES / CHUNK)

#define NTILES (NROWS / ROWS_PER_CTA)   // 512
#define NBIG 296                        // full tiles (one per wave-1 slot)
#define NSPLIT (NTILES - NBIG)          // 216 split tiles
#define SPLITC 6                        // piece A: chunks [0,6); piece B: [6,8)
#define GRID (NBIG + 2 * NSPLIT)        // 728

#define BSTRIDE 144
#define BUF_SPLIT (CHUNK * BSTRIDE)          // 18432 B per split
#define SM_B 0
#define SM_C (4 * BUF_SPLIT)                 // 73728: ||e||^2 (4 KB)
#define SM_IDX (SM_C + 4096)                 // 77824: per-row argmin / flag
#define SM_TOTAL (SM_IDX + ROWS_PER_CTA * 4)

// ---------------- device scratch ----------------
__device__ __half g_Bh[KCODES * DIM];
__device__ __half g_Bl[KCODES * DIM];
__device__ float g_c[KCODES];
__device__ unsigned long long g_key[NSPLIT * ROWS_PER_CTA];
__device__ unsigned int g_ctr[NSPLIT];

// ---------------- asm helpers ----------------
__device__ __forceinline__ uint32_t smem_u32(const void* p) {
    uint32_t a;
    asm("{ .reg .u64 t; cvta.to.shared.u64 t, %1; cvt.u32.u64 %0, t; }" : "=r"(a) : "l"(p));
    return a;
}
__device__ __forceinline__ void mma16816(float* d, const uint32_t* a, const uint32_t* b) {
    asm volatile(
        "mma.sync.aligned.m16n8k16.row.col.f32.f16.f16.f32 "
        "{%0,%1,%2,%3}, {%4,%5,%6,%7}, {%8,%9}, {%0,%1,%2,%3};"
        : "+f"(d[0]), "+f"(d[1]), "+f"(d[2]), "+f"(d[3])
        : "r"(a[0]), "r"(a[1]), "r"(a[2]), "r"(a[3]), "r"(b[0]), "r"(b[1]));
}
__device__ __forceinline__ void ldsm_x4(uint32_t* r, uint32_t addr) {
    asm volatile("ldmatrix.sync.aligned.m8n8.x4.shared.b16 {%0,%1,%2,%3}, [%4];"
                 : "=r"(r[0]), "=r"(r[1]), "=r"(r[2]), "=r"(r[3]) : "r"(addr));
}
#define CP_ASYNC16(dst, src) \
    asm volatile("cp.async.cg.shared.global [%0], [%1], 16;" :: "r"(dst), "l"(src))
#define CP_COMMIT() asm volatile("cp.async.commit_group;" ::: "memory")
#define CP_WAIT0()  asm volatile("cp.async.wait_group 0;" ::: "memory")

__device__ __forceinline__ void splitf2(float2 v, uint32_t& hh, uint32_t& ll) {
    __half hx = __float2half_rn(v.x);
    __half hy = __float2half_rn(v.y);
    __half lx = __float2half_rn(v.x - __half2float(hx));
    __half ly = __float2half_rn(v.y - __half2float(hy));
    __half2 H = __halves2half2(hx, hy);
    __half2 L = __halves2half2(lx, ly);
    hh = *(uint32_t*)&H;
    ll = *(uint32_t*)&L;
}
__device__ __forceinline__ uint32_t ordf(float f) {
    uint32_t u = __float_as_uint(f);
    return (u & 0x80000000u) ? ~u : (u | 0x80000000u);
}

// ---------------- prep / init kernels ----------------
__global__ void prep_codes(const float* __restrict__ emb) {
    const int wid = threadIdx.x >> 5;
    const int lane = threadIdx.x & 31;
    const int code = blockIdx.x * 8 + wid * 2 + (lane >> 4);
    const int seg = lane & 15;
    float4 v = ((const float4*)(emb + (size_t)code * DIM))[seg];
    float c = v.x * v.x + v.y * v.y + v.z * v.z + v.w * v.w;
#pragma unroll
    for (int off = 8; off; off >>= 1) c += __shfl_down_sync(0xffffffffu, c, off, 16);
    if (seg == 0) g_c[code] = c;

    float t[4] = {-2.f * v.x, -2.f * v.y, -2.f * v.z, -2.f * v.w};
    uint32_t h01, l01, h23, l23;
    splitf2(make_float2(t[0], t[1]), h01, l01);
    splitf2(make_float2(t[2], t[3]), h23, l23);
    uint32_t* bh = (uint32_t*)(g_Bh + (size_t)code * DIM) + seg * 2;
    uint32_t* bl = (uint32_t*)(g_Bl + (size_t)code * DIM) + seg * 2;
    bh[0] = h01; bh[1] = h23;
    bl[0] = l01; bl[1] = l23;
}

__global__ void init_merge() {
    int i = blockIdx.x * 256 + threadIdx.x;
    g_key[i] = 0xFFFFFFFFFFFFFFFFull;
    if (threadIdx.x == 0) g_ctr[blockIdx.x] = 0;
}

// ---------------- main kernel ----------------
__device__ __forceinline__ void issue_B_copy(char* smem, int chunk, int buf, int tid) {
    const __half* srcs[2] = {g_Bh, g_Bl};
#pragma unroll
    for (int j = 0; j < 8; j++) {
        int op = j * THREADS + tid;
        int s = op >> 10;
        int rowcol = op & 1023;
        int row = rowcol >> 3;
        int col = rowcol & 7;
        uint32_t dst = smem_u32(smem + SM_B + (buf * 2 + s) * BUF_SPLIT
                                + row * BSTRIDE + col * 16);
        const char* src = (const char*)srcs[s]
                        + ((size_t)(chunk * CHUNK + row) * DIM + col * 8) * 2;
        CP_ASYNC16(dst, src);
    }
}

__device__ __forceinline__ void row_epilogue(
    int row, int widx,
    const float* __restrict__ inputs, const float* __restrict__ emb,
    float* __restrict__ out_q, float* __restrict__ out_idx, float* __restrict__ out_loss) {
    const float4* e4 = (const float4*)(emb + (size_t)widx * DIM);
    const float4* x4 = (const float4*)(inputs + (size_t)row * DIM);
    float4* o4 = (float4*)(out_q + (size_t)row * DIM);
    float loss = 0.f;
#pragma unroll
    for (int j = 0; j < 16; j++) {
        float4 xv = x4[j];
        float4 ev = e4[j];
        float dx = ev.x - xv.x, dy = ev.y - xv.y;
        float dz = ev.z - xv.z, dw = ev.w - xv.w;
        loss += dx * dx + dy * dy + dz * dz + dw * dw;
        o4[j] = make_float4(xv.x + dx, xv.y + dy, xv.z + dz, xv.w + dw);
    }
    out_idx[row] = (float)widx;
    out_loss[row] = 1.25f * loss;
}

__global__ __launch_bounds__(THREADS, 2)
void vq_main(const float* __restrict__ inputs,
             const float* __restrict__ emb,
             float* __restrict__ out_q,
             float* __restrict__ out_idx,
             float* __restrict__ out_loss) {
    extern __shared__ __align__(16) char smem[];
    const int tid = threadIdx.x;
    const int wid = tid >> 5;
    const int lane = tid & 31;
    const int q = lane & 3;
    const int lr = lane >> 2;

    // work mapping
    const int b = blockIdx.x;
    int tile, c0, c1;
    bool is_split;
    if (b < NBIG)            { tile = b;                 c0 = 0;      c1 = NCHUNK; is_split = false; }
    else if (b < NBIG + NSPLIT) { tile = NBIG + (b - NBIG); c0 = 0;   c1 = SPLITC; is_split = true; }
    else                     { tile = NBIG + (b - NBIG - NSPLIT); c0 = SPLITC; c1 = NCHUNK; is_split = true; }

    float* s_c = (float*)(smem + SM_C);
    int* s_idx = (int*)(smem + SM_IDX);

#pragma unroll
    for (int i = tid; i < KCODES; i += THREADS) s_c[i] = g_c[i];

    issue_B_copy(smem, c0, 0, tid);
    CP_COMMIT();

    // A fragments from fp32 inputs, converted in registers
    uint32_t ah[2][4][4], al[2][4][4];
    {
        const int row0 = tile * ROWS_PER_CTA + wid * 32 + lr;
#pragma unroll
        for (int mt = 0; mt < 2; mt++) {
#pragma unroll
            for (int kt = 0; kt < 4; kt++) {
                size_t base = (size_t)(row0 + mt * 16) * DIM + kt * 16 + 2 * q;
                splitf2(*(const float2*)(inputs + base),               ah[mt][kt][0], al[mt][kt][0]);
                splitf2(*(const float2*)(inputs + base + 8 * DIM),     ah[mt][kt][1], al[mt][kt][1]);
                splitf2(*(const float2*)(inputs + base + 8),           ah[mt][kt][2], al[mt][kt][2]);
                splitf2(*(const float2*)(inputs + base + 8 * DIM + 8), ah[mt][kt][3], al[mt][kt][3]);
            }
        }
    }

    float best[4] = {3.4e38f, 3.4e38f, 3.4e38f, 3.4e38f};
    int bidx[4] = {0, 0, 0, 0};

    const uint32_t lbase = ((((lane >> 4) & 1) * 8 + (lane & 7)) * BSTRIDE)
                         + ((lane >> 3) & 1) * 16;

    for (int c = c0; c < c1; c++) {
        CP_WAIT0();
        __syncthreads();
        const int buf = (c - c0) & 1;
        if (c + 1 < c1) {
            issue_B_copy(smem, c + 1, buf ^ 1, tid);
            CP_COMMIT();
        }

        const uint32_t bh_base = smem_u32(smem + SM_B + (buf * 2 + 0) * BUF_SPLIT) + lbase;
        const uint32_t bl_base = smem_u32(smem + SM_B + (buf * 2 + 1) * BUF_SPLIT) + lbase;

#pragma unroll 2
        for (int ntp = 0; ntp < CHUNK / 16; ntp++) {
            const uint32_t poff = ntp * 16 * BSTRIDE;
            uint32_t bf[4][4];
            float acc[2][2][4];

            // init accumulators with ||e||^2 (replaces per-candidate FADD)
#pragma unroll
            for (int half = 0; half < 2; half++) {
                const int kb = c * CHUNK + (ntp * 2 + half) * 8;
                const float cc0 = s_c[kb + 2 * q];
                const float cc1 = s_c[kb + 2 * q + 1];
#pragma unroll
                for (int mt = 0; mt < 2; mt++) {
                    acc[half][mt][0] = cc0; acc[half][mt][1] = cc1;
                    acc[half][mt][2] = cc0; acc[half][mt][3] = cc1;
                }
            }

            // b_h: hh + lh products
#pragma unroll
            for (int kt = 0; kt < 4; kt++) ldsm_x4(bf[kt], bh_base + poff + kt * 32);
#pragma unroll
            for (int half = 0; half < 2; half++)
#pragma unroll
                for (int mt = 0; mt < 2; mt++) {
#pragma unroll
                    for (int kt = 0; kt < 4; kt++) mma16816(acc[half][mt], ah[mt][kt], &bf[kt][2 * half]);
#pragma unroll
                    for (int kt = 0; kt < 4; kt++) mma16816(acc[half][mt], al[mt][kt], &bf[kt][2 * half]);
                }
            // b_l: hl product only
#pragma unroll
            for (int kt = 0; kt < 4; kt++) ldsm_x4(bf[kt], bl_base + poff + kt * 32);
#pragma unroll
            for (int half = 0; half < 2; half++)
#pragma unroll
                for (int mt = 0; mt < 2; mt++)
#pragma unroll
                    for (int kt = 0; kt < 4; kt++) mma16816(acc[half][mt], ah[mt][kt], &bf[kt][2 * half]);

            // argmin update
#pragma unroll
            for (int half = 0; half < 2; half++) {
                const int kb = c * CHUNK + (ntp * 2 + half) * 8;
#pragma unroll
                for (int mt = 0; mt < 2; mt++) {
#pragma unroll
                    for (int h2 = 0; h2 < 2; h2++) {
                        const int slot = mt * 2 + h2;
                        float s0 = acc[half][mt][h2 * 2 + 0];
                        float s1 = acc[half][mt][h2 * 2 + 1];
                        if (s0 < best[slot]) { best[slot] = s0; bidx[slot] = kb + 2 * q; }
                        if (s1 < best[slot]) { best[slot] = s1; bidx[slot] = kb + 2 * q + 1; }
                    }
                }
            }
        }
        __syncthreads();
    }

    // reduce argmin across the 4 lanes of each quad-row
#pragma unroll
    for (int off = 1; off <= 2; off <<= 1) {
#pragma unroll
        for (int s = 0; s < 4; s++) {
            float ob = __shfl_xor_sync(0xffffffffu, best[s], off);
            int oi = __shfl_xor_sync(0xffffffffu, bidx[s], off);
            if (ob < best[s] || (ob == best[s] && oi < bidx[s])) {
                best[s] = ob; bidx[s] = oi;
            }
        }
    }

    if (!is_split) {
        if (q == 0) {
            const int rbase = wid * 32 + lr;
#pragma unroll
            for (int s = 0; s < 4; s++) s_idx[rbase + s * 8] = bidx[s];
        }
        __syncthreads();
        row_epilogue(tile * ROWS_PER_CTA + tid, s_idx[tid],
                     inputs, emb, out_q, out_idx, out_loss);
    } else {
        const int st = tile - NBIG;
        if (q == 0) {
            const int rbase = st * ROWS_PER_CTA + wid * 32 + lr;
#pragma unroll
            for (int s = 0; s < 4; s++) {
                unsigned long long key =
                    ((unsigned long long)ordf(best[s]) << 32) | (unsigned)bidx[s];
                atomicMin(&g_key[rbase + s * 8], key);
            }
        }
        __threadfence();
        __syncthreads();
        if (tid == 0) s_idx[0] = (int)atomicAdd(&g_ctr[st], 1u);
        __syncthreads();
        if (s_idx[0] == 1) {       // this CTA finished second: do the epilogue
            __threadfence();
            int widx = (int)(unsigned)(g_key[st * ROWS_PER_CTA + tid] & 0xFFFFFFFFull);
            row_epilogue(tile * ROWS_PER_CTA + tid, widx,
                         inputs, emb, out_q, out_idx, out_loss);
        }
    }
}

// ---------------- launcher ----------------
extern "C" void kernel_launch(void* const* d_in, const int* in_sizes, int n_in,
                              void* d_out, int out_size) {
    const float* inputs = (const float*)d_in[0];
    const float* emb = (const float*)d_in[1];
    float* out = (float*)d_out;

    float* out_q = out;
    float* out_idx = out + (size_t)NROWS * DIM;
    float* out_loss = out_idx + NROWS;

    static bool attr_set = false;
    if (!attr_set) {
        cudaFuncSetAttribute(vq_main, cudaFuncAttributeMaxDynamicSharedMemorySize, SM_TOTAL);
        attr_set = true;
    }

    prep_codes<<<KCODES / 8, 128>>>(emb);
    init_merge<<<NSPLIT, 256>>>();
    vq_main<<<GRID, THREADS, SM_TOTAL>>>(inputs, emb, out_q, out_idx, out_loss);
}

// round 8
// speedup vs baseline: 3.8079x; 1.0100x over previous
#include <cuda_runtime.h>
#include <cuda_fp16.h>
#include <cstdint>

// VQ argmin via HMMA, 2-way fp16 split, 3 products (hh, lh, hl).
// Mixed-granularity scheduling (296 full tiles + 216 split 3/4+1/4 tiles,
// merged via exact u64 atomicMin). Single fused prep kernel; one barrier/chunk.

#define DIM 64
#define KCODES 1024
#define NROWS (256*512)
#define ROWS_PER_CTA 256
#define THREADS 256
#define CHUNK 128
#define NCHUNK (KCODES / CHUNK)

#define NTILES (NROWS / ROWS_PER_CTA)   // 512
#define NBIG 296
#define NSPLIT (NTILES - NBIG)          // 216
#define SPLITC 6
#define GRID (NBIG + 2 * NSPLIT)        // 728

#define BSTRIDE 144
#define BUF_SPLIT (CHUNK * BSTRIDE)
#define SM_B 0
#define SM_C (4 * BUF_SPLIT)
#define SM_IDX (SM_C + 4096)
#define SM_TOTAL (SM_IDX + ROWS_PER_CTA * 4)

// ---------------- device scratch ----------------
__device__ __half g_Bh[KCODES * DIM];
__device__ __half g_Bl[KCODES * DIM];
__device__ float g_c[KCODES];
__device__ unsigned long long g_key[NSPLIT * ROWS_PER_CTA];
__device__ unsigned int g_ctr[NSPLIT];

// ---------------- asm helpers ----------------
__device__ __forceinline__ uint32_t smem_u32(const void* p) {
    uint32_t a;
    asm("{ .reg .u64 t; cvta.to.shared.u64 t, %1; cvt.u32.u64 %0, t; }" : "=r"(a) : "l"(p));
    return a;
}
__device__ __forceinline__ void mma16816(float* d, const uint32_t* a, const uint32_t* b) {
    asm volatile(
        "mma.sync.aligned.m16n8k16.row.col.f32.f16.f16.f32 "
        "{%0,%1,%2,%3}, {%4,%5,%6,%7}, {%8,%9}, {%0,%1,%2,%3};"
        : "+f"(d[0]), "+f"(d[1]), "+f"(d[2]), "+f"(d[3])
        : "r"(a[0]), "r"(a[1]), "r"(a[2]), "r"(a[3]), "r"(b[0]), "r"(b[1]));
}
__device__ __forceinline__ void ldsm_x4(uint32_t* r, uint32_t addr) {
    asm volatile("ldmatrix.sync.aligned.m8n8.x4.shared.b16 {%0,%1,%2,%3}, [%4];"
                 : "=r"(r[0]), "=r"(r[1]), "=r"(r[2]), "=r"(r[3]) : "r"(addr));
}
#define CP_ASYNC16(dst, src) \
    asm volatile("cp.async.cg.shared.global [%0], [%1], 16;" :: "r"(dst), "l"(src))
#define CP_COMMIT() asm volatile("cp.async.commit_group;" ::: "memory")
#define CP_WAIT0()  asm volatile("cp.async.wait_group 0;" ::: "memory")

__device__ __forceinline__ void splitf2(float2 v, uint32_t& hh, uint32_t& ll) {
    __half hx = __float2half_rn(v.x);
    __half hy = __float2half_rn(v.y);
    __half lx = __float2half_rn(v.x - __half2float(hx));
    __half ly = __float2half_rn(v.y - __half2float(hy));
    __half2 H = __halves2half2(hx, hy);
    __half2 L = __halves2half2(lx, ly);
    hh = *(uint32_t*)&H;
    ll = *(uint32_t*)&L;
}
__device__ __forceinline__ uint32_t ordf(float f) {
    uint32_t u = __float_as_uint(f);
    return (u & 0x80000000u) ? ~u : (u | 0x80000000u);
}

// ---------------- fused prep: codes (blocks 0..63) + merge init (64..279) ----------------
#define PREP_CODE_BLOCKS 64
#define PREP_GRID (PREP_CODE_BLOCKS + NSPLIT)

__global__ void prep_all(const float* __restrict__ emb) {
    if (blockIdx.x < PREP_CODE_BLOCKS) {
        const int wid = threadIdx.x >> 5;
        const int lane = threadIdx.x & 31;
        const int code = blockIdx.x * 16 + wid * 2 + (lane >> 4);
        const int seg = lane & 15;
        float4 v = ((const float4*)(emb + (size_t)code * DIM))[seg];
        float c = v.x * v.x + v.y * v.y + v.z * v.z + v.w * v.w;
#pragma unroll
        for (int off = 8; off; off >>= 1) c += __shfl_down_sync(0xffffffffu, c, off, 16);
        if (seg == 0) g_c[code] = c;

        float t[4] = {-2.f * v.x, -2.f * v.y, -2.f * v.z, -2.f * v.w};
        uint32_t h01, l01, h23, l23;
        splitf2(make_float2(t[0], t[1]), h01, l01);
        splitf2(make_float2(t[2], t[3]), h23, l23);
        uint32_t* bh = (uint32_t*)(g_Bh + (size_t)code * DIM) + seg * 2;
        uint32_t* bl = (uint32_t*)(g_Bl + (size_t)code * DIM) + seg * 2;
        bh[0] = h01; bh[1] = h23;
        bl[0] = l01; bl[1] = l23;
    } else {
        const int sb = blockIdx.x - PREP_CODE_BLOCKS;
        g_key[sb * ROWS_PER_CTA + threadIdx.x] = 0xFFFFFFFFFFFFFFFFull;
        if (threadIdx.x == 0) g_ctr[sb] = 0;
    }
}

// ---------------- main kernel ----------------
__device__ __forceinline__ void issue_B_copy(char* smem, int chunk, int buf, int tid) {
    const __half* srcs[2] = {g_Bh, g_Bl};
#pragma unroll
    for (int j = 0; j < 8; j++) {
        int op = j * THREADS + tid;
        int s = op >> 10;
        int rowcol = op & 1023;
        int row = rowcol >> 3;
        int col = rowcol & 7;
        uint32_t dst = smem_u32(smem + SM_B + (buf * 2 + s) * BUF_SPLIT
                                + row * BSTRIDE + col * 16);
        const char* src = (const char*)srcs[s]
                        + ((size_t)(chunk * CHUNK + row) * DIM + col * 8) * 2;
        CP_ASYNC16(dst, src);
    }
}

__device__ __forceinline__ void row_epilogue(
    int row, int widx,
    const float* __restrict__ inputs, const float* __restrict__ emb,
    float* __restrict__ out_q, float* __restrict__ out_idx, float* __restrict__ out_loss) {
    const float4* e4 = (const float4*)(emb + (size_t)widx * DIM);
    const float4* x4 = (const float4*)(inputs + (size_t)row * DIM);
    float4* o4 = (float4*)(out_q + (size_t)row * DIM);
    float loss = 0.f;
#pragma unroll
    for (int j = 0; j < 16; j++) {
        float4 xv = x4[j];
        float4 ev = e4[j];
        float dx = ev.x - xv.x, dy = ev.y - xv.y;
        float dz = ev.z - xv.z, dw = ev.w - xv.w;
        loss += dx * dx + dy * dy + dz * dz + dw * dw;
        o4[j] = make_float4(xv.x + dx, xv.y + dy, xv.z + dz, xv.w + dw);
    }
    out_idx[row] = (float)widx;
    out_loss[row] = 1.25f * loss;
}

__global__ __launch_bounds__(THREADS, 2)
void vq_main(const float* __restrict__ inputs,
             const float* __restrict__ emb,
             float* __restrict__ out_q,
             float* __restrict__ out_idx,
             float* __restrict__ out_loss) {
    extern __shared__ __align__(16) char smem[];
    const int tid = threadIdx.x;
    const int wid = tid >> 5;
    const int lane = tid & 31;
    const int q = lane & 3;
    const int lr = lane >> 2;

    const int b = blockIdx.x;
    int tile, c0, c1;
    bool is_split;
    if (b < NBIG)               { tile = b;                          c0 = 0;      c1 = NCHUNK; is_split = false; }
    else if (b < NBIG + NSPLIT) { tile = NBIG + (b - NBIG);          c0 = 0;      c1 = SPLITC; is_split = true; }
    else                        { tile = NBIG + (b - NBIG - NSPLIT); c0 = SPLITC; c1 = NCHUNK; is_split = true; }

    float* s_c = (float*)(smem + SM_C);
    int* s_idx = (int*)(smem + SM_IDX);

#pragma unroll
    for (int i = tid; i < KCODES; i += THREADS) s_c[i] = g_c[i];

    issue_B_copy(smem, c0, 0, tid);
    CP_COMMIT();

    // A fragments from fp32 inputs, converted in registers
    uint32_t ah[2][4][4], al[2][4][4];
    {
        const int row0 = tile * ROWS_PER_CTA + wid * 32 + lr;
#pragma unroll
        for (int mt = 0; mt < 2; mt++) {
#pragma unroll
            for (int kt = 0; kt < 4; kt++) {
                size_t base = (size_t)(row0 + mt * 16) * DIM + kt * 16 + 2 * q;
                splitf2(*(const float2*)(inputs + base),               ah[mt][kt][0], al[mt][kt][0]);
                splitf2(*(const float2*)(inputs + base + 8 * DIM),     ah[mt][kt][1], al[mt][kt][1]);
                splitf2(*(const float2*)(inputs + base + 8),           ah[mt][kt][2], al[mt][kt][2]);
                splitf2(*(const float2*)(inputs + base + 8 * DIM + 8), ah[mt][kt][3], al[mt][kt][3]);
            }
        }
    }

    float best[4] = {3.4e38f, 3.4e38f, 3.4e38f, 3.4e38f};
    int bidx[4] = {0, 0, 0, 0};

    const uint32_t lbase = ((((lane >> 4) & 1) * 8 + (lane & 7)) * BSTRIDE)
                         + ((lane >> 3) & 1) * 16;

    for (int c = c0; c < c1; c++) {
        CP_WAIT0();
        __syncthreads();                       // single barrier per chunk
        const int buf = (c - c0) & 1;
        if (c + 1 < c1) {
            issue_B_copy(smem, c + 1, buf ^ 1, tid);
            CP_COMMIT();
        }

        const uint32_t bh_base = smem_u32(smem + SM_B + (buf * 2 + 0) * BUF_SPLIT) + lbase;
        const uint32_t bl_base = smem_u32(smem + SM_B + (buf * 2 + 1) * BUF_SPLIT) + lbase;

#pragma unroll 2
        for (int ntp = 0; ntp < CHUNK / 16; ntp++) {
            const uint32_t poff = ntp * 16 * BSTRIDE;
            uint32_t bf[4][4];
            float acc[2][2][4];

            // preload the 4 ||e||^2 constants for this ntp, init accumulators
            const int kb0 = c * CHUNK + ntp * 16;
            float cc[2][2];
            cc[0][0] = s_c[kb0 + 2 * q];
            cc[0][1] = s_c[kb0 + 2 * q + 1];
            cc[1][0] = s_c[kb0 + 8 + 2 * q];
            cc[1][1] = s_c[kb0 + 8 + 2 * q + 1];
#pragma unroll
            for (int half = 0; half < 2; half++)
#pragma unroll
                for (int mt = 0; mt < 2; mt++) {
                    acc[half][mt][0] = cc[half][0]; acc[half][mt][1] = cc[half][1];
                    acc[half][mt][2] = cc[half][0]; acc[half][mt][3] = cc[half][1];
                }

            // b_h: hh + lh products
#pragma unroll
            for (int kt = 0; kt < 4; kt++) ldsm_x4(bf[kt], bh_base + poff + kt * 32);
#pragma unroll
            for (int half = 0; half < 2; half++)
#pragma unroll
                for (int mt = 0; mt < 2; mt++) {
#pragma unroll
                    for (int kt = 0; kt < 4; kt++) mma16816(acc[half][mt], ah[mt][kt], &bf[kt][2 * half]);
#pragma unroll
                    for (int kt = 0; kt < 4; kt++) mma16816(acc[half][mt], al[mt][kt], &bf[kt][2 * half]);
                }
            // b_l: hl product only
#pragma unroll
            for (int kt = 0; kt < 4; kt++) ldsm_x4(bf[kt], bl_base + poff + kt * 32);
#pragma unroll
            for (int half = 0; half < 2; half++)
#pragma unroll
                for (int mt = 0; mt < 2; mt++)
#pragma unroll
                    for (int kt = 0; kt < 4; kt++) mma16816(acc[half][mt], ah[mt][kt], &bf[kt][2 * half]);

            // argmin update
#pragma unroll
            for (int half = 0; half < 2; half++) {
                const int kb = kb0 + half * 8;
#pragma unroll
                for (int mt = 0; mt < 2; mt++) {
#pragma unroll
                    for (int h2 = 0; h2 < 2; h2++) {
                        const int slot = mt * 2 + h2;
                        float s0 = acc[half][mt][h2 * 2 + 0];
                        float s1 = acc[half][mt][h2 * 2 + 1];
                        if (s0 < best[slot]) { best[slot] = s0; bidx[slot] = kb + 2 * q; }
                        if (s1 < best[slot]) { best[slot] = s1; bidx[slot] = kb + 2 * q + 1; }
                    }
                }
            }
        }
    }
    __syncthreads();   // protect s_idx reuse below

    // reduce argmin across the 4 lanes of each quad-row
#pragma unroll
    for (int off = 1; off <= 2; off <<= 1) {
#pragma unroll
        for (int s = 0; s < 4; s++) {
            float ob = __shfl_xor_sync(0xffffffffu, best[s], off);
            int oi = __shfl_xor_sync(0xffffffffu, bidx[s], off);
            if (ob < best[s] || (ob == best[s] && oi < bidx[s])) {
                best[s] = ob; bidx[s] = oi;
            }
        }
    }

    if (!is_split) {
        if (q == 0) {
            const int rbase = wid * 32 + lr;
#pragma unroll
            for (int s = 0; s < 4; s++) s_idx[rbase + s * 8] = bidx[s];
        }
        __syncthreads();
        row_epilogue(tile * ROWS_PER_CTA + tid, s_idx[tid],
                     inputs, emb, out_q, out_idx, out_loss);
    } else {
        const int st = tile - NBIG;
        if (q == 0) {
            const int rbase = st * ROWS_PER_CTA + wid * 32 + lr;
#pragma unroll
            for (int s = 0; s < 4; s++) {
                unsigned long long key =
                    ((unsigned long long)ordf(best[s]) << 32) | (unsigned)bidx[s];
                atomicMin(&g_key[rbase + s * 8], key);
            }
        }
        __threadfence();
        __syncthreads();
        if (tid == 0) s_idx[0] = (int)atomicAdd(&g_ctr[st], 1u);
        __syncthreads();
        if (s_idx[0] == 1) {
            __threadfence();
            int widx = (int)(unsigned)(g_key[st * ROWS_PER_CTA + tid] & 0xFFFFFFFFull);
            row_epilogue(tile * ROWS_PER_CTA + tid, widx,
                         inputs, emb, out_q, out_idx, out_loss);
        }
    }
}

// ---------------- launcher ----------------
extern "C" void kernel_launch(void* const* d_in, const int* in_sizes, int n_in,
                              void* d_out, int out_size) {
    const float* inputs = (const float*)d_in[0];
    const float* emb = (const float*)d_in[1];
    float* out = (float*)d_out;

    float* out_q = out;
    float* out_idx = out + (size_t)NROWS * DIM;
    float* out_loss = out_idx + NROWS;

    static bool attr_set = false;
    if (!attr_set) {
        cudaFuncSetAttribute(vq_main, cudaFuncAttributeMaxDynamicSharedMemorySize, SM_TOTAL);
        attr_set = true;
    }

    prep_all<<<PREP_GRID, 256>>>(emb);
    vq_main<<<GRID, THREADS, SM_TOTAL>>>(inputs, emb, out_q, out_idx, out_loss);
}

// round 9
// speedup vs baseline: 3.8162x; 1.0022x over previous
#include <cuda_runtime.h>
#include <cuda_fp16.h>
#include <cstdint>

// VQ argmin via HMMA, 2-way fp16 split, 3 products (hh, lh, hl).
// Mixed-granularity scheduling (296 full tiles + 216 split 3/4+1/4 tiles).
// This round: kt-outer MMA interleave (4 independent acc chains) + leaner argmin.

#define DIM 64
#define KCODES 1024
#define NROWS (256*512)
#define ROWS_PER_CTA 256
#define THREADS 256
#define CHUNK 128
#define NCHUNK (KCODES / CHUNK)

#define NTILES (NROWS / ROWS_PER_CTA)   // 512
#define NBIG 296
#define NSPLIT (NTILES - NBIG)          // 216
#define SPLITC 6
#define GRID (NBIG + 2 * NSPLIT)        // 728

#define BSTRIDE 144
#define BUF_SPLIT (CHUNK * BSTRIDE)
#define SM_B 0
#define SM_C (4 * BUF_SPLIT)
#define SM_IDX (SM_C + 4096)
#define SM_TOTAL (SM_IDX + ROWS_PER_CTA * 4)

// ---------------- device scratch ----------------
__device__ __half g_Bh[KCODES * DIM];
__device__ __half g_Bl[KCODES * DIM];
__device__ float g_c[KCODES];
__device__ unsigned long long g_key[NSPLIT * ROWS_PER_CTA];
__device__ unsigned int g_ctr[NSPLIT];

// ---------------- asm helpers ----------------
__device__ __forceinline__ uint32_t smem_u32(const void* p) {
    uint32_t a;
    asm("{ .reg .u64 t; cvta.to.shared.u64 t, %1; cvt.u32.u64 %0, t; }" : "=r"(a) : "l"(p));
    return a;
}
__device__ __forceinline__ void mma16816(float* d, const uint32_t* a, const uint32_t* b) {
    asm volatile(
        "mma.sync.aligned.m16n8k16.row.col.f32.f16.f16.f32 "
        "{%0,%1,%2,%3}, {%4,%5,%6,%7}, {%8,%9}, {%0,%1,%2,%3};"
        : "+f"(d[0]), "+f"(d[1]), "+f"(d[2]), "+f"(d[3])
        : "r"(a[0]), "r"(a[1]), "r"(a[2]), "r"(a[3]), "r"(b[0]), "r"(b[1]));
}
__device__ __forceinline__ void ldsm_x4(uint32_t* r, uint32_t addr) {
    asm volatile("ldmatrix.sync.aligned.m8n8.x4.shared.b16 {%0,%1,%2,%3}, [%4];"
                 : "=r"(r[0]), "=r"(r[1]), "=r"(r[2]), "=r"(r[3]) : "r"(addr));
}
#define CP_ASYNC16(dst, src) \
    asm volatile("cp.async.cg.shared.global [%0], [%1], 16;" :: "r"(dst), "l"(src))
#define CP_COMMIT() asm volatile("cp.async.commit_group;" ::: "memory")
#define CP_WAIT0()  asm volatile("cp.async.wait_group 0;" ::: "memory")

__device__ __forceinline__ void splitf2(float2 v, uint32_t& hh, uint32_t& ll) {
    __half hx = __float2half_rn(v.x);
    __half hy = __float2half_rn(v.y);
    __half lx = __float2half_rn(v.x - __half2float(hx));
    __half ly = __float2half_rn(v.y - __half2float(hy));
    __half2 H = __halves2half2(hx, hy);
    __half2 L = __halves2half2(lx, ly);
    hh = *(uint32_t*)&H;
    ll = *(uint32_t*)&L;
}
__device__ __forceinline__ uint32_t ordf(float f) {
    uint32_t u = __float_as_uint(f);
    return (u & 0x80000000u) ? ~u : (u | 0x80000000u);
}

// ---------------- fused prep ----------------
#define PREP_CODE_BLOCKS 64
#define PREP_GRID (PREP_CODE_BLOCKS + NSPLIT)

__global__ void prep_all(const float* __restrict__ emb) {
    if (blockIdx.x < PREP_CODE_BLOCKS) {
        const int wid = threadIdx.x >> 5;
        const int lane = threadIdx.x & 31;
        const int code = blockIdx.x * 16 + wid * 2 + (lane >> 4);
        const int seg = lane & 15;
        float4 v = ((const float4*)(emb + (size_t)code * DIM))[seg];
        float c = v.x * v.x + v.y * v.y + v.z * v.z + v.w * v.w;
#pragma unroll
        for (int off = 8; off; off >>= 1) c += __shfl_down_sync(0xffffffffu, c, off, 16);
        if (seg == 0) g_c[code] = c;

        float t[4] = {-2.f * v.x, -2.f * v.y, -2.f * v.z, -2.f * v.w};
        uint32_t h01, l01, h23, l23;
        splitf2(make_float2(t[0], t[1]), h01, l01);
        splitf2(make_float2(t[2], t[3]), h23, l23);
        uint32_t* bh = (uint32_t*)(g_Bh + (size_t)code * DIM) + seg * 2;
        uint32_t* bl = (uint32_t*)(g_Bl + (size_t)code * DIM) + seg * 2;
        bh[0] = h01; bh[1] = h23;
        bl[0] = l01; bl[1] = l23;
    } else {
        const int sb = blockIdx.x - PREP_CODE_BLOCKS;
        g_key[sb * ROWS_PER_CTA + threadIdx.x] = 0xFFFFFFFFFFFFFFFFull;
        if (threadIdx.x == 0) g_ctr[sb] = 0;
    }
}

// ---------------- main kernel ----------------
__device__ __forceinline__ void issue_B_copy(char* smem, int chunk, int buf, int tid) {
    const __half* srcs[2] = {g_Bh, g_Bl};
#pragma unroll
    for (int j = 0; j < 8; j++) {
        int op = j * THREADS + tid;
        int s = op >> 10;
        int rowcol = op & 1023;
        int row = rowcol >> 3;
        int col = rowcol & 7;
        uint32_t dst = smem_u32(smem + SM_B + (buf * 2 + s) * BUF_SPLIT
                                + row * BSTRIDE + col * 16);
        const char* src = (const char*)srcs[s]
                        + ((size_t)(chunk * CHUNK + row) * DIM + col * 8) * 2;
        CP_ASYNC16(dst, src);
    }
}

__device__ __forceinline__ void row_epilogue(
    int row, int widx,
    const float* __restrict__ inputs, const float* __restrict__ emb,
    float* __restrict__ out_q, float* __restrict__ out_idx, float* __restrict__ out_loss) {
    const float4* e4 = (const float4*)(emb + (size_t)widx * DIM);
    const float4* x4 = (const float4*)(inputs + (size_t)row * DIM);
    float4* o4 = (float4*)(out_q + (size_t)row * DIM);
    float loss = 0.f;
#pragma unroll
    for (int j = 0; j < 16; j++) {
        float4 xv = x4[j];
        float4 ev = e4[j];
        float dx = ev.x - xv.x, dy = ev.y - xv.y;
        float dz = ev.z - xv.z, dw = ev.w - xv.w;
        loss += dx * dx + dy * dy + dz * dz + dw * dw;
        o4[j] = make_float4(xv.x + dx, xv.y + dy, xv.z + dz, xv.w + dw);
    }
    out_idx[row] = (float)widx;
    out_loss[row] = 1.25f * loss;
}

__global__ __launch_bounds__(THREADS, 2)
void vq_main(const float* __restrict__ inputs,
             const float* __restrict__ emb,
             float* __restrict__ out_q,
             float* __restrict__ out_idx,
             float* __restrict__ out_loss) {
    extern __shared__ __align__(16) char smem[];
    const int tid = threadIdx.x;
    const int wid = tid >> 5;
    const int lane = tid & 31;
    const int q = lane & 3;
    const int kq = 2 * q;
    const int lr = lane >> 2;

    const int b = blockIdx.x;
    int tile, c0, c1;
    bool is_split;
    if (b < NBIG)               { tile = b;                          c0 = 0;      c1 = NCHUNK; is_split = false; }
    else if (b < NBIG + NSPLIT) { tile = NBIG + (b - NBIG);          c0 = 0;      c1 = SPLITC; is_split = true; }
    else                        { tile = NBIG + (b - NBIG - NSPLIT); c0 = SPLITC; c1 = NCHUNK; is_split = true; }

    float* s_c = (float*)(smem + SM_C);
    int* s_idx = (int*)(smem + SM_IDX);

#pragma unroll
    for (int i = tid; i < KCODES; i += THREADS) s_c[i] = g_c[i];

    issue_B_copy(smem, c0, 0, tid);
    CP_COMMIT();

    // A fragments from fp32 inputs, converted in registers
    uint32_t ah[2][4][4], al[2][4][4];
    {
        const int row0 = tile * ROWS_PER_CTA + wid * 32 + lr;
#pragma unroll
        for (int mt = 0; mt < 2; mt++) {
#pragma unroll
            for (int kt = 0; kt < 4; kt++) {
                size_t base = (size_t)(row0 + mt * 16) * DIM + kt * 16 + kq;
                splitf2(*(const float2*)(inputs + base),               ah[mt][kt][0], al[mt][kt][0]);
                splitf2(*(const float2*)(inputs + base + 8 * DIM),     ah[mt][kt][1], al[mt][kt][1]);
                splitf2(*(const float2*)(inputs + base + 8),           ah[mt][kt][2], al[mt][kt][2]);
                splitf2(*(const float2*)(inputs + base + 8 * DIM + 8), ah[mt][kt][3], al[mt][kt][3]);
            }
        }
    }

    float best[4] = {3.4e38f, 3.4e38f, 3.4e38f, 3.4e38f};
    int bidx[4] = {0, 0, 0, 0};

    const uint32_t lbase = ((((lane >> 4) & 1) * 8 + (lane & 7)) * BSTRIDE)
                         + ((lane >> 3) & 1) * 16;

    for (int c = c0; c < c1; c++) {
        CP_WAIT0();
        __syncthreads();
        const int buf = (c - c0) & 1;
        if (c + 1 < c1) {
            issue_B_copy(smem, c + 1, buf ^ 1, tid);
            CP_COMMIT();
        }

        const uint32_t bh_base = smem_u32(smem + SM_B + (buf * 2 + 0) * BUF_SPLIT) + lbase;
        const uint32_t bl_base = smem_u32(smem + SM_B + (buf * 2 + 1) * BUF_SPLIT) + lbase;

#pragma unroll 2
        for (int ntp = 0; ntp < CHUNK / 16; ntp++) {
            const uint32_t poff = ntp * 16 * BSTRIDE;
            uint32_t bf[4][4];
            float acc[2][2][4];

            const int kb0 = c * CHUNK + ntp * 16;
            float cc[2][2];
            cc[0][0] = s_c[kb0 + kq];
            cc[0][1] = s_c[kb0 + kq + 1];
            cc[1][0] = s_c[kb0 + 8 + kq];
            cc[1][1] = s_c[kb0 + 8 + kq + 1];
#pragma unroll
            for (int half = 0; half < 2; half++)
#pragma unroll
                for (int mt = 0; mt < 2; mt++) {
                    acc[half][mt][0] = cc[half][0]; acc[half][mt][1] = cc[half][1];
                    acc[half][mt][2] = cc[half][0]; acc[half][mt][3] = cc[half][1];
                }

            // b_h: hh + lh products; kt-outer => 4 independent acc chains interleaved
#pragma unroll
            for (int kt = 0; kt < 4; kt++) ldsm_x4(bf[kt], bh_base + poff + kt * 32);
#pragma unroll
            for (int kt = 0; kt < 4; kt++)
#pragma unroll
                for (int half = 0; half < 2; half++)
#pragma unroll
                    for (int mt = 0; mt < 2; mt++)
                        mma16816(acc[half][mt], ah[mt][kt], &bf[kt][2 * half]);
#pragma unroll
            for (int kt = 0; kt < 4; kt++)
#pragma unroll
                for (int half = 0; half < 2; half++)
#pragma unroll
                    for (int mt = 0; mt < 2; mt++)
                        mma16816(acc[half][mt], al[mt][kt], &bf[kt][2 * half]);

            // b_l: hl product only
#pragma unroll
            for (int kt = 0; kt < 4; kt++) ldsm_x4(bf[kt], bl_base + poff + kt * 32);
#pragma unroll
            for (int kt = 0; kt < 4; kt++)
#pragma unroll
                for (int half = 0; half < 2; half++)
#pragma unroll
                    for (int mt = 0; mt < 2; mt++)
                        mma16816(acc[half][mt], ah[mt][kt], &bf[kt][2 * half]);

            // argmin update: pair-min then single compare per slot
#pragma unroll
            for (int half = 0; half < 2; half++) {
                const int kbq = kb0 + half * 8 + kq;
#pragma unroll
                for (int mt = 0; mt < 2; mt++) {
#pragma unroll
                    for (int h2 = 0; h2 < 2; h2++) {
                        const int slot = mt * 2 + h2;
                        float s0 = acc[half][mt][h2 * 2 + 0];
                        float s1 = acc[half][mt][h2 * 2 + 1];
                        float m = fminf(s0, s1);
                        if (m < best[slot]) {
                            best[slot] = m;
                            bidx[slot] = kbq + (s1 < s0 ? 1 : 0);
                        }
                    }
                }
            }
        }
    }
    __syncthreads();   // protect s_idx reuse below

    // reduce argmin across the 4 lanes of each quad-row
#pragma unroll
    for (int off = 1; off <= 2; off <<= 1) {
#pragma unroll
        for (int s = 0; s < 4; s++) {
            float ob = __shfl_xor_sync(0xffffffffu, best[s], off);
            int oi = __shfl_xor_sync(0xffffffffu, bidx[s], off);
            if (ob < best[s] || (ob == best[s] && oi < bidx[s])) {
                best[s] = ob; bidx[s] = oi;
            }
        }
    }

    if (!is_split) {
        if (q == 0) {
            const int rbase = wid * 32 + lr;
#pragma unroll
            for (int s = 0; s < 4; s++) s_idx[rbase + s * 8] = bidx[s];
        }
        __syncthreads();
        row_epilogue(tile * ROWS_PER_CTA + tid, s_idx[tid],
                     inputs, emb, out_q, out_idx, out_loss);
    } else {
        const int st = tile - NBIG;
        if (q == 0) {
            const int rbase = st * ROWS_PER_CTA + wid * 32 + lr;
#pragma unroll
            for (int s = 0; s < 4; s++) {
                unsigned long long key =
                    ((unsigned long long)ordf(best[s]) << 32) | (unsigned)bidx[s];
                atomicMin(&g_key[rbase + s * 8], key);
            }
        }
        __threadfence();
        __syncthreads();
        if (tid == 0) s_idx[0] = (int)atomicAdd(&g_ctr[st], 1u);
        __syncthreads();
        if (s_idx[0] == 1) {
            __threadfence();
            int widx = (int)(unsigned)(g_key[st * ROWS_PER_CTA + tid] & 0xFFFFFFFFull);
            row_epilogue(tile * ROWS_PER_CTA + tid, widx,
                         inputs, emb, out_q, out_idx, out_loss);
        }
    }
}

// ---------------- launcher ----------------
extern "C" void kernel_launch(void* const* d_in, const int* in_sizes, int n_in,
                              void* d_out, int out_size) {
    const float* inputs = (const float*)d_in[0];
    const float* emb = (const float*)d_in[1];
    float* out = (float*)d_out;

    float* out_q = out;
    float* out_idx = out + (size_t)NROWS * DIM;
    float* out_loss = out_idx + NROWS;

    static bool attr_set = false;
    if (!attr_set) {
        cudaFuncSetAttribute(vq_main, cudaFuncAttributeMaxDynamicSharedMemorySize, SM_TOTAL);
        attr_set = true;
    }

    prep_all<<<PREP_GRID, 256>>>(emb);
    vq_main<<<GRID, THREADS, SM_TOTAL>>>(inputs, emb, out_q, out_idx, out_loss);
}

// round 10
// speedup vs baseline: 3.9720x; 1.0408x over previous
#include <cuda_runtime.h>
#include <cuda_fp16.h>
#include <cstdint>

// VQ argmin via HMMA, 2-way fp16 split, 3 products (hh, lh, hl).
// This round: 128-thread CTAs (4 warps, 128 rows, CHUNK=64) -> 4 CTAs/SM with
// independent barriers (phase diversity); (6,5,5) split scheduling on 592 slots.

#define DIM 64
#define KCODES 1024
#define NROWS (256*512)
#define ROWS_PER_CTA 128
#define THREADS 128
#define CHUNK 64
#define NCHUNK (KCODES / CHUNK)        // 16

#define NTILES (NROWS / ROWS_PER_CTA)  // 1024
#define NBIG 592
#define NSPLIT (NTILES - NBIG)         // 432
#define GRID (NBIG + 3 * NSPLIT)       // 1888
// split-piece chunk ranges: [0,6), [6,11), [11,16)

#define BSTRIDE 144
#define BUF_SPLIT (CHUNK * BSTRIDE)    // 9216
#define SM_B 0                         // 2 bufs x 2 splits = 36864
#define SM_C (4 * BUF_SPLIT)           // 36864 (4 KB table)
#define SM_IDX (SM_C + 4096)           // 40960
#define SM_TOTAL (SM_IDX + ROWS_PER_CTA * 4)   // 41472

// ---------------- device scratch ----------------
__device__ __half g_Bh[KCODES * DIM];
__device__ __half g_Bl[KCODES * DIM];
__device__ float g_c[KCODES];
__device__ unsigned long long g_key[NSPLIT * ROWS_PER_CTA];
__device__ unsigned int g_ctr[NSPLIT];

// ---------------- asm helpers ----------------
__device__ __forceinline__ uint32_t smem_u32(const void* p) {
    uint32_t a;
    asm("{ .reg .u64 t; cvta.to.shared.u64 t, %1; cvt.u32.u64 %0, t; }" : "=r"(a) : "l"(p));
    return a;
}
__device__ __forceinline__ void mma16816(float* d, const uint32_t* a, const uint32_t* b) {
    asm volatile(
        "mma.sync.aligned.m16n8k16.row.col.f32.f16.f16.f32 "
        "{%0,%1,%2,%3}, {%4,%5,%6,%7}, {%8,%9}, {%0,%1,%2,%3};"
        : "+f"(d[0]), "+f"(d[1]), "+f"(d[2]), "+f"(d[3])
        : "r"(a[0]), "r"(a[1]), "r"(a[2]), "r"(a[3]), "r"(b[0]), "r"(b[1]));
}
__device__ __forceinline__ void ldsm_x4(uint32_t* r, uint32_t addr) {
    asm volatile("ldmatrix.sync.aligned.m8n8.x4.shared.b16 {%0,%1,%2,%3}, [%4];"
                 : "=r"(r[0]), "=r"(r[1]), "=r"(r[2]), "=r"(r[3]) : "r"(addr));
}
#define CP_ASYNC16(dst, src) \
    asm volatile("cp.async.cg.shared.global [%0], [%1], 16;" :: "r"(dst), "l"(src))
#define CP_COMMIT() asm volatile("cp.async.commit_group;" ::: "memory")
#define CP_WAIT0()  asm volatile("cp.async.wait_group 0;" ::: "memory")

__device__ __forceinline__ void splitf2(float2 v, uint32_t& hh, uint32_t& ll) {
    __half hx = __float2half_rn(v.x);
    __half hy = __float2half_rn(v.y);
    __half lx = __float2half_rn(v.x - __half2float(hx));
    __half ly = __float2half_rn(v.y - __half2float(hy));
    __half2 H = __halves2half2(hx, hy);
    __half2 L = __halves2half2(lx, ly);
    hh = *(uint32_t*)&H;
    ll = *(uint32_t*)&L;
}
__device__ __forceinline__ uint32_t ordf(float f) {
    uint32_t u = __float_as_uint(f);
    return (u & 0x80000000u) ? ~u : (u | 0x80000000u);
}

// ---------------- fused prep: codes (blocks 0..63) + merge init ----------------
#define PREP_CODE_BLOCKS 64
#define PREP_GRID (PREP_CODE_BLOCKS + NSPLIT)

__global__ void prep_all(const float* __restrict__ emb) {
    if (blockIdx.x < PREP_CODE_BLOCKS) {
        const int wid = threadIdx.x >> 5;
        const int lane = threadIdx.x & 31;
        const int code = blockIdx.x * 16 + wid * 2 + (lane >> 4);
        const int seg = lane & 15;
        float4 v = ((const float4*)(emb + (size_t)code * DIM))[seg];
        float c = v.x * v.x + v.y * v.y + v.z * v.z + v.w * v.w;
#pragma unroll
        for (int off = 8; off; off >>= 1) c += __shfl_down_sync(0xffffffffu, c, off, 16);
        if (seg == 0) g_c[code] = c;

        float t[4] = {-2.f * v.x, -2.f * v.y, -2.f * v.z, -2.f * v.w};
        uint32_t h01, l01, h23, l23;
        splitf2(make_float2(t[0], t[1]), h01, l01);
        splitf2(make_float2(t[2], t[3]), h23, l23);
        uint32_t* bh = (uint32_t*)(g_Bh + (size_t)code * DIM) + seg * 2;
        uint32_t* bl = (uint32_t*)(g_Bl + (size_t)code * DIM) + seg * 2;
        bh[0] = h01; bh[1] = h23;
        bl[0] = l01; bl[1] = l23;
    } else {
        const int sb = blockIdx.x - PREP_CODE_BLOCKS;
        if (threadIdx.x < ROWS_PER_CTA)
            g_key[sb * ROWS_PER_CTA + threadIdx.x] = 0xFFFFFFFFFFFFFFFFull;
        if (threadIdx.x == 0) g_ctr[sb] = 0;
    }
}

// ---------------- main kernel ----------------
__device__ __forceinline__ void issue_B_copy(char* smem, int chunk, int buf, int tid) {
    const __half* srcs[2] = {g_Bh, g_Bl};
#pragma unroll
    for (int j = 0; j < 8; j++) {
        int op = j * THREADS + tid;          // 0..1023
        int s = op >> 9;                     // split
        int rowcol = op & 511;               // row*8 + col16
        int row = rowcol >> 3;
        int col = rowcol & 7;
        uint32_t dst = smem_u32(smem + SM_B + (buf * 2 + s) * BUF_SPLIT
                                + row * BSTRIDE + col * 16);
        const char* src = (const char*)srcs[s]
                        + ((size_t)(chunk * CHUNK + row) * DIM + col * 8) * 2;
        CP_ASYNC16(dst, src);
    }
}

__device__ __forceinline__ void row_epilogue(
    int row, int widx,
    const float* __restrict__ inputs, const float* __restrict__ emb,
    float* __restrict__ out_q, float* __restrict__ out_idx, float* __restrict__ out_loss) {
    const float4* e4 = (const float4*)(emb + (size_t)widx * DIM);
    const float4* x4 = (const float4*)(inputs + (size_t)row * DIM);
    float4* o4 = (float4*)(out_q + (size_t)row * DIM);
    float loss = 0.f;
#pragma unroll
    for (int j = 0; j < 16; j++) {
        float4 xv = x4[j];
        float4 ev = e4[j];
        float dx = ev.x - xv.x, dy = ev.y - xv.y;
        float dz = ev.z - xv.z, dw = ev.w - xv.w;
        loss += dx * dx + dy * dy + dz * dz + dw * dw;
        o4[j] = make_float4(xv.x + dx, xv.y + dy, xv.z + dz, xv.w + dw);
    }
    out_idx[row] = (float)widx;
    out_loss[row] = 1.25f * loss;
}

__global__ __launch_bounds__(THREADS, 4)
void vq_main(const float* __restrict__ inputs,
             const float* __restrict__ emb,
             float* __restrict__ out_q,
             float* __restrict__ out_idx,
             float* __restrict__ out_loss) {
    extern __shared__ __align__(16) char smem[];
    const int tid = threadIdx.x;
    const int wid = tid >> 5;
    const int lane = tid & 31;
    const int q = lane & 3;
    const int kq = 2 * q;
    const int lr = lane >> 2;

    // work mapping: [0,592) full; then 432 x [0,6), 432 x [6,11), 432 x [11,16)
    const int b = blockIdx.x;
    int tile, c0, c1;
    bool is_split;
    if (b < NBIG) {
        tile = b; c0 = 0; c1 = NCHUNK; is_split = false;
    } else {
        const int p = b - NBIG;
        const int cls = p / NSPLIT;          // 0,1,2
        const int st = p - cls * NSPLIT;
        tile = NBIG + st;
        is_split = true;
        c0 = (cls == 0) ? 0 : (cls == 1 ? 6 : 11);
        c1 = (cls == 0) ? 6 : (cls == 1 ? 11 : 16);
    }

    float* s_c = (float*)(smem + SM_C);
    int* s_idx = (int*)(smem + SM_IDX);

#pragma unroll
    for (int i = tid; i < KCODES; i += THREADS) s_c[i] = g_c[i];

    issue_B_copy(smem, c0, 0, tid);
    CP_COMMIT();

    // A fragments from fp32 inputs, converted in registers
    uint32_t ah[2][4][4], al[2][4][4];
    {
        const int row0 = tile * ROWS_PER_CTA + wid * 32 + lr;
#pragma unroll
        for (int mt = 0; mt < 2; mt++) {
#pragma unroll
            for (int kt = 0; kt < 4; kt++) {
                size_t base = (size_t)(row0 + mt * 16) * DIM + kt * 16 + kq;
                splitf2(*(const float2*)(inputs + base),               ah[mt][kt][0], al[mt][kt][0]);
                splitf2(*(const float2*)(inputs + base + 8 * DIM),     ah[mt][kt][1], al[mt][kt][1]);
                splitf2(*(const float2*)(inputs + base + 8),           ah[mt][kt][2], al[mt][kt][2]);
                splitf2(*(const float2*)(inputs + base + 8 * DIM + 8), ah[mt][kt][3], al[mt][kt][3]);
            }
        }
    }

    float best[4] = {3.4e38f, 3.4e38f, 3.4e38f, 3.4e38f};
    int bidx[4] = {0, 0, 0, 0};

    const uint32_t lbase = ((((lane >> 4) & 1) * 8 + (lane & 7)) * BSTRIDE)
                         + ((lane >> 3) & 1) * 16;

    for (int c = c0; c < c1; c++) {
        CP_WAIT0();
        __syncthreads();
        const int buf = (c - c0) & 1;
        if (c + 1 < c1) {
            issue_B_copy(smem, c + 1, buf ^ 1, tid);
            CP_COMMIT();
        }

        const uint32_t bh_base = smem_u32(smem + SM_B + (buf * 2 + 0) * BUF_SPLIT) + lbase;
        const uint32_t bl_base = smem_u32(smem + SM_B + (buf * 2 + 1) * BUF_SPLIT) + lbase;

#pragma unroll 2
        for (int ntp = 0; ntp < CHUNK / 16; ntp++) {
            const uint32_t poff = ntp * 16 * BSTRIDE;
            uint32_t bf[4][4];
            float acc[2][2][4];

            const int kb0 = c * CHUNK + ntp * 16;
            float cc[2][2];
            cc[0][0] = s_c[kb0 + kq];
            cc[0][1] = s_c[kb0 + kq + 1];
            cc[1][0] = s_c[kb0 + 8 + kq];
            cc[1][1] = s_c[kb0 + 8 + kq + 1];
#pragma unroll
            for (int half = 0; half < 2; half++)
#pragma unroll
                for (int mt = 0; mt < 2; mt++) {
                    acc[half][mt][0] = cc[half][0]; acc[half][mt][1] = cc[half][1];
                    acc[half][mt][2] = cc[half][0]; acc[half][mt][3] = cc[half][1];
                }

            // b_h: hh + lh products
#pragma unroll
            for (int kt = 0; kt < 4; kt++) ldsm_x4(bf[kt], bh_base + poff + kt * 32);
#pragma unroll
            for (int kt = 0; kt < 4; kt++)
#pragma unroll
                for (int half = 0; half < 2; half++)
#pragma unroll
                    for (int mt = 0; mt < 2; mt++)
                        mma16816(acc[half][mt], ah[mt][kt], &bf[kt][2 * half]);
#pragma unroll
            for (int kt = 0; kt < 4; kt++)
#pragma unroll
                for (int half = 0; half < 2; half++)
#pragma unroll
                    for (int mt = 0; mt < 2; mt++)
                        mma16816(acc[half][mt], al[mt][kt], &bf[kt][2 * half]);

            // b_l: hl product only
#pragma unroll
            for (int kt = 0; kt < 4; kt++) ldsm_x4(bf[kt], bl_base + poff + kt * 32);
#pragma unroll
            for (int kt = 0; kt < 4; kt++)
#pragma unroll
                for (int half = 0; half < 2; half++)
#pragma unroll
                    for (int mt = 0; mt < 2; mt++)
                        mma16816(acc[half][mt], ah[mt][kt], &bf[kt][2 * half]);

            // argmin: 4-way fminf tree per slot (bit-identical selection order)
#pragma unroll
            for (int mt = 0; mt < 2; mt++) {
#pragma unroll
                for (int h2 = 0; h2 < 2; h2++) {
                    const int slot = mt * 2 + h2;
                    float s0 = acc[0][mt][h2 * 2 + 0];
                    float s1 = acc[0][mt][h2 * 2 + 1];
                    float s2 = acc[1][mt][h2 * 2 + 0];
                    float s3 = acc[1][mt][h2 * 2 + 1];
                    float m01 = fminf(s0, s1);
                    float m23 = fminf(s2, s3);
                    float m = fminf(m01, m23);
                    if (m < best[slot]) {
                        int i01 = kb0 + kq + (s1 < s0 ? 1 : 0);
                        int i23 = kb0 + 8 + kq + (s3 < s2 ? 1 : 0);
                        bidx[slot] = (m23 < m01) ? i23 : i01;
                        best[slot] = m;
                    }
                }
            }
        }
    }
    __syncthreads();   // protect s_idx reuse below

    // reduce argmin across the 4 lanes of each quad-row
#pragma unroll
    for (int off = 1; off <= 2; off <<= 1) {
#pragma unroll
        for (int s = 0; s < 4; s++) {
            float ob = __shfl_xor_sync(0xffffffffu, best[s], off);
            int oi = __shfl_xor_sync(0xffffffffu, bidx[s], off);
            if (ob < best[s] || (ob == best[s] && oi < bidx[s])) {
                best[s] = ob; bidx[s] = oi;
            }
        }
    }

    if (!is_split) {
        if (q == 0) {
            const int rbase = wid * 32 + lr;
#pragma unroll
            for (int s = 0; s < 4; s++) s_idx[rbase + s * 8] = bidx[s];
        }
        __syncthreads();
        row_epilogue(tile * ROWS_PER_CTA + tid, s_idx[tid],
                     inputs, emb, out_q, out_idx, out_loss);
    } else {
        const int st = tile - NBIG;
        if (q == 0) {
            const int rbase = st * ROWS_PER_CTA + wid * 32 + lr;
#pragma unroll
            for (int s = 0; s < 4; s++) {
                unsigned long long key =
                    ((unsigned long long)ordf(best[s]) << 32) | (unsigned)bidx[s];
                atomicMin(&g_key[rbase + s * 8], key);
            }
        }
        __threadfence();
        __syncthreads();
        if (tid == 0) s_idx[0] = (int)atomicAdd(&g_ctr[st], 1u);
        __syncthreads();
        if (s_idx[0] == 2) {       // last of the 3 pieces does the epilogue
            __threadfence();
            int widx = (int)(unsigned)(g_key[st * ROWS_PER_CTA + tid] & 0xFFFFFFFFull);
            row_epilogue(tile * ROWS_PER_CTA + tid, widx,
                         inputs, emb, out_q, out_idx, out_loss);
        }
    }
}

// ---------------- launcher ----------------
extern "C" void kernel_launch(void* const* d_in, const int* in_sizes, int n_in,
                              void* d_out, int out_size) {
    const float* inputs = (const float*)d_in[0];
    const float* emb = (const float*)d_in[1];
    float* out = (float*)d_out;

    float* out_q = out;
    float* out_idx = out + (size_t)NROWS * DIM;
    float* out_loss = out_idx + NROWS;

    prep_all<<<PREP_GRID, 256>>>(emb);
    vq_main<<<GRID, THREADS, SM_TOTAL>>>(inputs, emb, out_q, out_idx, out_loss);
}